// round 11
// baseline (speedup 1.0000x reference)
#include <cuda_runtime.h>
#include <cstdint>
#include <math.h>

#define BB 8
#define NN 2048
#define UU 256
#define MROWS (BB*NN)     // 16384
#define MAXNBR 128

// ---------------- device scratch ---------------------------------------------
__device__ float g_h  [MROWS*UU];
__device__ float g_y  [MROWS*UU];
__device__ float g_qkv[3*MROWS*UU];
__device__ float g_t3 [3*MROWS*UU];
__device__ uint4 g_kvp[BB*32*4*256];    // packed kv planes per batch (4MB)
__device__ uint4 g_wp [16*32*4*256];    // packed split weights (8MB)
__device__ int   g_cols[MROWS*MAXNBR];
__device__ int   g_cnt [MROWS];

// ---------------- helpers -----------------------------------------------------
__device__ __forceinline__ void tsplit(float x, uint32_t& hi, uint32_t& lo) {
    asm("cvt.rna.tf32.f32 %0, %1;" : "=r"(hi) : "f"(x));
    float r = x - __uint_as_float(hi);
    asm("cvt.rna.tf32.f32 %0, %1;" : "=r"(lo) : "f"(r));
}
__device__ __forceinline__ void mma8(float c[4], const uint32_t a[4], const uint32_t b[2]) {
    asm volatile(
        "mma.sync.aligned.m16n8k8.row.col.f32.tf32.tf32.f32 "
        "{%0,%1,%2,%3},{%4,%5,%6,%7},{%8,%9},{%0,%1,%2,%3};"
        : "+f"(c[0]), "+f"(c[1]), "+f"(c[2]), "+f"(c[3])
        : "r"(a[0]), "r"(a[1]), "r"(a[2]), "r"(a[3]), "r"(b[0]), "r"(b[1]));
}
__device__ __forceinline__ uint32_t smem_u32(const void* p) {
    uint32_t a;
    asm("{ .reg .u64 t; cvta.to.shared.u64 t, %1; cvt.u32.u64 %0, t; }" : "=r"(a) : "l"(p));
    return a;
}
#define CP_ASYNC16(dst, src) \
    asm volatile("cp.async.cg.shared.global [%0], [%1], 16;" :: "r"(dst), "l"(src))
#define CP_COMMIT()  asm volatile("cp.async.commit_group;" ::: "memory")
#define CP_WAIT0()   asm volatile("cp.async.wait_group 0;" ::: "memory")

// ---------------- weight pack: split W[k][n] into fragment-major planes -------
// cell(ksg, q, n) = {hi(W[8ksg+q][n]), lo, hi(W[8ksg+q+4][n]), lo}
struct WTptrs { const float* src[16]; };
__global__ void pack_w(WTptrs p, uint4* __restrict__ dst) {
    int m = blockIdx.y;
    int c = blockIdx.x * 256 + threadIdx.x;      // 0..32767
    int n   = c & 255;
    int q   = (c >> 8) & 3;
    int ksg = c >> 10;
    const float* S = p.src[m];
    float v0 = S[(size_t)(8 * ksg + q) * UU + n];
    float v1 = S[(size_t)(8 * ksg + q + 4) * UU + n];
    uint32_t h0, l0, h1, l1;
    tsplit(v0, h0, l0); tsplit(v1, h1, l1);
    dst[(size_t)m * 32768 + c] = make_uint4(h0, l0, h1, l1);
}

// ---------------- CSR build: float4 + warp scan -------------------------------
__global__ void csr_build(const float* __restrict__ adj) {
    int r    = blockIdx.x * 8 + (threadIdx.x >> 5);
    int lane = threadIdx.x & 31;
    const float4* row = (const float4*)(adj + (size_t)r * NN);
    int base = 0;
    for (int c0 = 0; c0 < NN / 4; c0 += 32) {
        float4 v = row[c0 + lane];
        unsigned m4 = (v.x != 0.f ? 1u : 0u) | (v.y != 0.f ? 2u : 0u)
                    | (v.z != 0.f ? 4u : 0u) | (v.w != 0.f ? 8u : 0u);
        int cnt4 = __popc(m4);
        int inc = cnt4;
#pragma unroll
        for (int o = 1; o < 32; o <<= 1) {
            int t = __shfl_up_sync(0xffffffffu, inc, o);
            if (lane >= o) inc += t;
        }
        int pos = base + inc - cnt4;
        int colbase = (c0 + lane) * 4;
        if (m4 & 1) { if (pos < MAXNBR) g_cols[r * MAXNBR + pos] = colbase;     pos++; }
        if (m4 & 2) { if (pos < MAXNBR) g_cols[r * MAXNBR + pos] = colbase + 1; pos++; }
        if (m4 & 4) { if (pos < MAXNBR) g_cols[r * MAXNBR + pos] = colbase + 2; pos++; }
        if (m4 & 8) { if (pos < MAXNBR) g_cols[r * MAXNBR + pos] = colbase + 3; pos++; }
        base += __shfl_sync(0xffffffffu, inc, 31);
    }
    if (lane == 0) g_cnt[r] = base < MAXNBR ? base : MAXNBR;
}

// ---------------- spmm: adj @ x, float4, 4 rows/block, MLP=4 ------------------
__global__ void __launch_bounds__(256) spmm(const float* __restrict__ x,
                                            float* __restrict__ out) {
    __shared__ int cols[4][MAXNBR];
    int sub = threadIdx.x >> 6;
    int t   = threadIdx.x & 63;
    int r      = blockIdx.x * 4 + sub;
    int rr     = r & (MROWS - 1);
    int stream = r >> 14;
    int cnt = g_cnt[rr];
    for (int i = t; i < cnt; i += 64) cols[sub][i] = g_cols[rr * MAXNBR + i];
    __syncthreads();
    const float* xb = x + ((size_t)stream * MROWS + (size_t)(rr & ~(NN - 1))) * UU;
    float4 s0 = {0,0,0,0}, s1 = {0,0,0,0}, s2 = {0,0,0,0}, s3 = {0,0,0,0};
    int j = 0;
    for (; j + 4 <= cnt; j += 4) {
        float4 v0 = *((const float4*)(xb + (size_t)cols[sub][j]     * UU) + t);
        float4 v1 = *((const float4*)(xb + (size_t)cols[sub][j + 1] * UU) + t);
        float4 v2 = *((const float4*)(xb + (size_t)cols[sub][j + 2] * UU) + t);
        float4 v3 = *((const float4*)(xb + (size_t)cols[sub][j + 3] * UU) + t);
        s0.x += v0.x; s0.y += v0.y; s0.z += v0.z; s0.w += v0.w;
        s1.x += v1.x; s1.y += v1.y; s1.z += v1.z; s1.w += v1.w;
        s2.x += v2.x; s2.y += v2.y; s2.z += v2.z; s2.w += v2.w;
        s3.x += v3.x; s3.y += v3.y; s3.z += v3.z; s3.w += v3.w;
    }
    for (; j < cnt; j++) {
        float4 v0 = *((const float4*)(xb + (size_t)cols[sub][j] * UU) + t);
        s0.x += v0.x; s0.y += v0.y; s0.z += v0.z; s0.w += v0.w;
    }
    float4 o = {(s0.x + s1.x) + (s2.x + s3.x), (s0.y + s1.y) + (s2.y + s3.y),
                (s0.z + s1.z) + (s2.z + s3.z), (s0.w + s1.w) + (s2.w + s3.w)};
    *((float4*)(out + (size_t)r * UU) + t) = o;
}

// ---------------- 3xTF32 GEMM, fragment-major smem, 2-stage pipeline ----------
// A: [2 buf][4 ks][4 q][128 r] uint4 cells, row 130 u4, ks 522 u4, buf 2088 u4.
// B: [2 buf][4 ks][4 q][ 64 n] uint4 cells, row  66 u4, ks 266 u4, buf 1064 u4.
struct GemmArgs {
    const float* A;
    const uint4* W0; const uint4* W1; const uint4* W2;   // packed weights
    const float* b0; const float* b1; const float* b2;
    float* C;
    const float* addsrc;
    const float* mask;
    const float* gamma; const float* beta; const float* mean; const float* var;
    int act0, act1, act2;
    int mm0, mm1, mm2;   // 0 none, 1 before act, 2 after act
    int ashared;
    int perBatchW;
};

#define A_U4   2088               // 4*522 (one stage)
#define B_U4   1064               // 4*266 (one stage)
#define SMEM_G (2 * (A_U4 + B_U4) * (int)sizeof(uint4))   // 100,864 B

__global__ void __launch_bounds__(256, 2) gemm6(GemmArgs g) {
    extern __shared__ __align__(16) uint4 sm4[];
    uint4* Asm = sm4;                       // 2 * A_U4
    uint4* Bsm = sm4 + 2 * A_U4;            // 2 * B_U4

    int tid  = threadIdx.x;
    int lane = tid & 31;
    int wid  = tid >> 5;
    int wm   = wid & 3;
    int wn   = wid >> 2;
    int q    = lane & 3;
    int rg   = lane >> 2;
    int row0 = blockIdx.x * 128;
    int col0 = blockIdx.y * 64;
    int stream  = blockIdx.x >> 7;
    int rlocal0 = row0 - stream * MROWS;

    const uint4* W = (stream == 0) ? g.W0 : (stream == 1 ? g.W1 : g.W2);
    if (g.perBatchW) W = g.W0 + (size_t)(rlocal0 / NN) * 32768;
    const float* Arow = g.A + (size_t)(g.ashared ? rlocal0 : row0) * UU;

    int fA_ks = tid & 3,  fA_r = tid >> 2;          // rows fA_r and fA_r+64
    int fB_n  = tid & 63, fB_q = (tid >> 6) & 3;
    int aoff  = q * 130 + wm * 32 + rg;
    int boff  = q * 66  + wn * 32 + rg;

    float acc[2][4][4];
#pragma unroll
    for (int i = 0; i < 2; i++)
#pragma unroll
        for (int j = 0; j < 4; j++)
#pragma unroll
            for (int e = 0; e < 4; e++) acc[i][j][e] = 0.f;

    // ---- prologue: prefetch tile 0 ----
    float4 pv[2][2];
    {
        const float4* s0 = (const float4*)(Arow + (size_t)fA_r * UU + fA_ks * 8);
        const float4* s1 = (const float4*)(Arow + (size_t)(fA_r + 64) * UU + fA_ks * 8);
        pv[0][0] = s0[0]; pv[0][1] = s0[1];
        pv[1][0] = s1[0]; pv[1][1] = s1[1];
        const uint4* wsrc = W + fB_q * 256 + col0 + fB_n;
        uint4* bdst = Bsm + fB_q * 66 + fB_n;
#pragma unroll
        for (int ksl = 0; ksl < 4; ksl++)
            CP_ASYNC16(smem_u32(bdst + ksl * 266), wsrc + ksl * 1024);
        CP_COMMIT();
    }

    for (int t0 = 0; t0 < 8; t0++) {
        int cur = t0 & 1;
        // split prefetched regs -> Asm[cur]
        {
            uint4* ab = Asm + cur * A_U4 + fA_ks * 522 + fA_r;
#pragma unroll
            for (int t = 0; t < 2; t++) {
                float4 v0 = pv[t][0], v1 = pv[t][1];
                uint32_t h0,l0,h1,l1,h2,l2,h3,l3,h4,l4,h5,l5,h6,l6,h7,l7;
                tsplit(v0.x,h0,l0); tsplit(v0.y,h1,l1); tsplit(v0.z,h2,l2); tsplit(v0.w,h3,l3);
                tsplit(v1.x,h4,l4); tsplit(v1.y,h5,l5); tsplit(v1.z,h6,l6); tsplit(v1.w,h7,l7);
                uint4* abr = ab + t * 64;
                abr[0 * 130] = make_uint4(h0, l0, h4, l4);
                abr[1 * 130] = make_uint4(h1, l1, h5, l5);
                abr[2 * 130] = make_uint4(h2, l2, h6, l6);
                abr[3 * 130] = make_uint4(h3, l3, h7, l7);
            }
        }
        CP_WAIT0();
        __syncthreads();

        // prefetch tile t0+1 (regs + cp.async) before mma
        if (t0 < 7) {
            int k0n = (t0 + 1) * 32;
            const float4* s0 = (const float4*)(Arow + (size_t)fA_r * UU + k0n + fA_ks * 8);
            const float4* s1 = (const float4*)(Arow + (size_t)(fA_r + 64) * UU + k0n + fA_ks * 8);
            pv[0][0] = s0[0]; pv[0][1] = s0[1];
            pv[1][0] = s1[0]; pv[1][1] = s1[1];
            const uint4* wsrc = W + (size_t)(k0n >> 3) * 1024 + fB_q * 256 + col0 + fB_n;
            uint4* bdst = Bsm + (cur ^ 1) * B_U4 + fB_q * 66 + fB_n;
#pragma unroll
            for (int ksl = 0; ksl < 4; ksl++)
                CP_ASYNC16(smem_u32(bdst + ksl * 266), wsrc + ksl * 1024);
            CP_COMMIT();
        }

        // mma over tile t0
#pragma unroll
        for (int ks = 0; ks < 4; ks++) {
            uint32_t ahi[2][4], alo[2][4], bhi[4][2], blo[4][2];
            const uint4* ap = Asm + cur * A_U4 + ks * 522 + aoff;
            const uint4* bp = Bsm + cur * B_U4 + ks * 266 + boff;
#pragma unroll
            for (int i = 0; i < 2; i++) {
                uint4 c0 = ap[i * 16];
                uint4 c1 = ap[i * 16 + 8];
                ahi[i][0] = c0.x; alo[i][0] = c0.y;
                ahi[i][2] = c0.z; alo[i][2] = c0.w;
                ahi[i][1] = c1.x; alo[i][1] = c1.y;
                ahi[i][3] = c1.z; alo[i][3] = c1.w;
            }
#pragma unroll
            for (int j = 0; j < 4; j++) {
                uint4 b = bp[j * 8];
                bhi[j][0] = b.x; blo[j][0] = b.y;
                bhi[j][1] = b.z; blo[j][1] = b.w;
            }
            // 3 passes: 8 independent mmas between dependent ones
#pragma unroll
            for (int i = 0; i < 2; i++)
#pragma unroll
                for (int j = 0; j < 4; j++) mma8(acc[i][j], alo[i], bhi[j]);
#pragma unroll
            for (int i = 0; i < 2; i++)
#pragma unroll
                for (int j = 0; j < 4; j++) mma8(acc[i][j], ahi[i], blo[j]);
#pragma unroll
            for (int i = 0; i < 2; i++)
#pragma unroll
                for (int j = 0; j < 4; j++) mma8(acc[i][j], ahi[i], bhi[j]);
        }
    }

    const float* bias = (stream == 0) ? g.b0 : (stream == 1 ? g.b1 : g.b2);
    int act = (stream == 0) ? g.act0 : (stream == 1 ? g.act1 : g.act2);
    int mm  = (stream == 0) ? g.mm0  : (stream == 1 ? g.mm1  : g.mm2);

#pragma unroll
    for (int i = 0; i < 2; i++) {
#pragma unroll
        for (int p = 0; p < 2; p++) {
            int roff  = wm * 32 + i * 16 + rg + p * 8;
            int rglob = row0 + roff;
            int rloc  = rlocal0 + roff;
            float mk = mm ? g.mask[rloc] : 1.f;
#pragma unroll
            for (int j = 0; j < 4; j++) {
#pragma unroll
                for (int e = 0; e < 2; e++) {
                    int cc = col0 + wn * 32 + j * 8 + q * 2 + e;
                    float v = acc[i][j][p * 2 + e];
                    if (bias)     v += bias[cc];
                    if (g.addsrc) v += g.addsrc[(size_t)rglob * UU + cc];
                    if (g.gamma)
                        v = g.gamma[cc] * (v - g.mean[cc]) * rsqrtf(g.var[cc] + 1e-3f)
                            + g.beta[cc];
                    if (mm == 1) v *= mk;
                    if (act)     v *= 1.f / (1.f + __expf(-v));
                    if (mm == 2) v *= mk;
                    g.C[(size_t)rglob * UU + cc] = v;
                }
            }
        }
    }
}

// ---------------- kv[b] = pk^T @ pv, written as packed planes -----------------
__global__ void __launch_bounds__(256, 2) kv_t(const float* __restrict__ pk,
                                               const float* __restrict__ pv,
                                               uint4* __restrict__ kvp) {
    __shared__ float Ps[32][72];
    __shared__ float Vs[32][72];
    int tid  = threadIdx.x;
    int lane = tid & 31;
    int wid  = tid >> 5;
    int wm   = wid & 1;
    int wn   = wid >> 1;
    int d0 = blockIdx.x * 64, e0 = blockIdx.y * 64, b = blockIdx.z;
    const float* pkb = pk + (size_t)b * NN * UU;
    const float* pvb = pv + (size_t)b * NN * UU;

    float acc[2][2][4];
#pragma unroll
    for (int i = 0; i < 2; i++)
#pragma unroll
        for (int j = 0; j < 2; j++)
#pragma unroll
            for (int e = 0; e < 4; e++) acc[i][j][e] = 0.f;

    int q = lane & 3, rg = lane >> 2;

    for (int n0 = 0; n0 < NN; n0 += 32) {
#pragma unroll
        for (int i = 0; i < 2; i++) {
            int idx = tid + i * 256;
            int kr = idx >> 4, dc = (idx & 15) * 4;
            *(float4*)&Ps[kr][dc] = *(const float4*)(pkb + (size_t)(n0 + kr) * UU + d0 + dc);
            *(float4*)&Vs[kr][dc] = *(const float4*)(pvb + (size_t)(n0 + kr) * UU + e0 + dc);
        }
        __syncthreads();
#pragma unroll
        for (int ks = 0; ks < 4; ks++) {
            int kk = ks * 8;
            uint32_t ahi[2][4], alo[2][4], bhi[2][2], blo[2][2];
#pragma unroll
            for (int i = 0; i < 2; i++) {
                int rr = wm * 32 + i * 16 + rg;
                tsplit(Ps[kk + q    ][rr    ], ahi[i][0], alo[i][0]);
                tsplit(Ps[kk + q    ][rr + 8], ahi[i][1], alo[i][1]);
                tsplit(Ps[kk + q + 4][rr    ], ahi[i][2], alo[i][2]);
                tsplit(Ps[kk + q + 4][rr + 8], ahi[i][3], alo[i][3]);
            }
#pragma unroll
            for (int j = 0; j < 2; j++) {
                int nn = wn * 16 + j * 8 + rg;
                tsplit(Vs[kk + q    ][nn], bhi[j][0], blo[j][0]);
                tsplit(Vs[kk + q + 4][nn], bhi[j][1], blo[j][1]);
            }
#pragma unroll
            for (int i = 0; i < 2; i++)
#pragma unroll
                for (int j = 0; j < 2; j++) {
                    mma8(acc[i][j], alo[i], bhi[j]);
                    mma8(acc[i][j], ahi[i], blo[j]);
                    mma8(acc[i][j], ahi[i], bhi[j]);
                }
        }
        __syncthreads();
    }

    // write packed cells: cell(ksg=d>>3, q=d&3, n=e), half = (d>>2)&1
    uint2* out = (uint2*)(kvp + (size_t)b * 32768);
#pragma unroll
    for (int i = 0; i < 2; i++)
#pragma unroll
        for (int p = 0; p < 2; p++) {
            int dd = d0 + wm * 32 + i * 16 + rg + p * 8;
            int cellb = ((dd >> 3) * 4 + (dd & 3)) * 256;
            int half  = (dd >> 2) & 1;
#pragma unroll
            for (int j = 0; j < 2; j++)
#pragma unroll
                for (int e = 0; e < 2; e++) {
                    int ee = e0 + wn * 16 + j * 8 + q * 2 + e;
                    float v = acc[i][j][p * 2 + e];
                    uint32_t hi, lo;
                    tsplit(v, hi, lo);
                    out[(size_t)(cellb + ee) * 2 + half] = make_uint2(hi, lo);
                }
        }
}

// ---------------- host orchestration -----------------------------------------
extern "C" void kernel_launch(void* const* d_in, const int* in_sizes, int n_in,
                              void* d_out, int out_size) {
    const float* x      = (const float*)d_in[0];
    const float* adj    = (const float*)d_in[1];
    const float* mask   = (const float*)d_in[2];
    const float* W_lin  = (const float*)d_in[3];
    const float* b_lin  = (const float*)d_in[4];
    const float* Wq_mp  = (const float*)d_in[5];
    const float* bq_mp  = (const float*)d_in[6];
    const float* Wk_mp  = (const float*)d_in[7];
    const float* bk_mp  = (const float*)d_in[8];
    const float* Wv_mp  = (const float*)d_in[9];
    const float* bv_mp  = (const float*)d_in[10];
    const float* Wk_att = (const float*)d_in[11];
    const float* Wv_att = (const float*)d_in[12];
    const float* Wq_att = (const float*)d_in[13];
    const float* Wo_att = (const float*)d_in[14];
    const float* gamma  = (const float*)d_in[15];
    const float* beta   = (const float*)d_in[16];
    const float* mean   = (const float*)d_in[17];
    const float* var    = (const float*)d_in[18];
    const float* W_proj = (const float*)d_in[19];
    const float* b_proj = (const float*)d_in[20];
    const float* W_res  = (const float*)d_in[21];
    const float* b_res  = (const float*)d_in[22];

    float *h, *y, *qkv, *t3;
    uint4 *kvp, *wp;
    cudaGetSymbolAddress((void**)&h,   g_h);
    cudaGetSymbolAddress((void**)&y,   g_y);
    cudaGetSymbolAddress((void**)&qkv, g_qkv);
    cudaGetSymbolAddress((void**)&t3,  g_t3);
    cudaGetSymbolAddress((void**)&kvp, g_kvp);
    cudaGetSymbolAddress((void**)&wp,  g_wp);

    const uint4* P_lin  = wp + 0  * 32768;
    const uint4* P_qmp  = wp + 1  * 32768;
    const uint4* P_kmp  = wp + 4  * 32768;
    const uint4* P_vmp  = wp + 7  * 32768;
    const uint4* P_katt = wp + 10 * 32768;
    const uint4* P_vatt = wp + 11 * 32768;
    const uint4* P_qatt = wp + 12 * 32768;
    const uint4* P_oatt = wp + 13 * 32768;
    const uint4* P_proj = wp + 14 * 32768;
    const uint4* P_res  = wp + 15 * 32768;

    {
        WTptrs p;
        p.src[0] = W_lin;
        p.src[1] = Wq_mp;  p.src[2] = Wq_mp + UU*UU;  p.src[3] = Wq_mp + 2*UU*UU;
        p.src[4] = Wk_mp;  p.src[5] = Wk_mp + UU*UU;  p.src[6] = Wk_mp + 2*UU*UU;
        p.src[7] = Wv_mp;  p.src[8] = Wv_mp + UU*UU;  p.src[9] = Wv_mp + 2*UU*UU;
        p.src[10] = Wk_att; p.src[11] = Wv_att; p.src[12] = Wq_att; p.src[13] = Wo_att;
        p.src[14] = W_proj; p.src[15] = W_res;
        pack_w<<<dim3(128, 16), 256>>>(p, wp);
    }

    cudaFuncSetAttribute(gemm6, cudaFuncAttributeMaxDynamicSharedMemorySize, SMEM_G);

    dim3 g1(MROWS / 128, UU / 64);       // 512 CTAs
    dim3 g3(3 * MROWS / 128, UU / 64);   // 1536 CTAs

    csr_build<<<MROWS / 8, 256>>>(adj);

    // h = x @ W_lin + b_lin
    { GemmArgs a = {}; a.A = x; a.W0 = P_lin; a.b0 = b_lin; a.C = h;
      gemm6<<<g1, 256, SMEM_G>>>(a); }

    // mp iteration 0: adj@h shared by all three streams
    spmm<<<MROWS / 4, 256>>>(h, t3);
    { GemmArgs a = {}; a.A = t3; a.ashared = 1;
      a.W0 = P_qmp; a.W1 = P_kmp; a.W2 = P_vmp;
      a.b0 = bq_mp; a.b1 = bk_mp; a.b2 = bv_mp;
      a.act0 = a.act1 = a.act2 = 1; a.C = qkv;
      gemm6<<<g3, 256, SMEM_G>>>(a); }

    // mp iterations 1..5
    for (int it = 1; it < 6; it++) {
        int i = it >> 1;
        spmm<<<3 * MROWS / 4, 256>>>(qkv, t3);
        GemmArgs a = {}; a.A = t3;
        a.W0 = P_qmp + (size_t)i * 32768;
        a.W1 = P_kmp + (size_t)i * 32768;
        a.W2 = P_vmp + (size_t)i * 32768;
        a.b0 = bq_mp + i * UU; a.b1 = bk_mp + i * UU; a.b2 = bv_mp + i * UU;
        a.act0 = a.act1 = a.act2 = 1;
        if (it == 5) { a.mm0 = a.mm1 = a.mm2 = 2; a.mask = mask; }
        a.C = qkv;
        gemm6<<<g3, 256, SMEM_G>>>(a);
    }

    // attention projections: pq = q@Wq ; pk = silu((k@Wk)*m) ; pv = (v@Wv)*m
    { GemmArgs a = {}; a.A = qkv;
      a.W0 = P_qatt; a.W1 = P_katt; a.W2 = P_vatt;
      a.act1 = 1; a.mm1 = 1; a.mm2 = 1; a.mask = mask;
      a.C = t3;
      gemm6<<<g3, 256, SMEM_G>>>(a); }

    // kv[b] = pk^T @ pv  (packed output)
    kv_t<<<dim3(UU / 64, UU / 64, BB), 256>>>(t3 + (size_t)MROWS * UU,
                                              t3 + (size_t)2 * MROWS * UU, kvp);

    // attn = pq @ kv[b]
    { GemmArgs a = {}; a.A = t3; a.W0 = kvp; a.perBatchW = 1; a.C = h;
      gemm6<<<g1, 256, SMEM_G>>>(a); }

    // y = BN(attn @ Wo + x)
    { GemmArgs a = {}; a.A = h; a.W0 = P_oatt; a.addsrc = x;
      a.gamma = gamma; a.beta = beta; a.mean = mean; a.var = var; a.C = y;
      gemm6<<<g1, 256, SMEM_G>>>(a); }

    // p = silu(y @ W_proj + b_proj)
    { GemmArgs a = {}; a.A = y; a.W0 = P_proj; a.b0 = b_proj; a.act0 = 1; a.C = t3;
      gemm6<<<g1, 256, SMEM_G>>>(a); }

    // out = (p + x @ W_res + b_res) * mask
    { GemmArgs a = {}; a.A = x; a.W0 = P_res; a.b0 = b_res; a.addsrc = t3;
      a.mm0 = 2; a.mask = mask; a.C = (float*)d_out;
      gemm6<<<g1, 256, SMEM_G>>>(a); }
}

// round 13
// speedup vs baseline: 1.3243x; 1.3243x over previous
#include <cuda_runtime.h>
#include <cuda_bf16.h>
#include <cstdint>
#include <math.h>

#define BB 8
#define NN 2048
#define UU 256
#define MROWS (BB*NN)     // 16384
#define MAXNBR 128

// ---------------- device scratch ---------------------------------------------
__device__ float g_h  [MROWS*UU];
__device__ float g_y  [MROWS*UU];
__device__ float g_qkv[3*MROWS*UU];
__device__ float g_t3 [3*MROWS*UU];
__device__ float g_kv [BB*UU*UU];        // float kv per batch
__device__ uint4 g_kvp[BB*16384];        // packed bf16 kv cells (2MB)
__device__ uint4 g_wp [16*16384];        // packed bf16 weight cells (4MB)
__device__ int   g_cols[MROWS*MAXNBR];
__device__ int   g_cnt [MROWS];

// ---------------- helpers -----------------------------------------------------
__device__ __forceinline__ void tsplit(float x, uint32_t& hi, uint32_t& lo) {
    asm("cvt.rna.tf32.f32 %0, %1;" : "=r"(hi) : "f"(x));
    float r = x - __uint_as_float(hi);
    asm("cvt.rna.tf32.f32 %0, %1;" : "=r"(lo) : "f"(r));
}
__device__ __forceinline__ void mma8(float c[4], const uint32_t a[4], const uint32_t b[2]) {
    asm volatile(
        "mma.sync.aligned.m16n8k8.row.col.f32.tf32.tf32.f32 "
        "{%0,%1,%2,%3},{%4,%5,%6,%7},{%8,%9},{%0,%1,%2,%3};"
        : "+f"(c[0]), "+f"(c[1]), "+f"(c[2]), "+f"(c[3])
        : "r"(a[0]), "r"(a[1]), "r"(a[2]), "r"(a[3]), "r"(b[0]), "r"(b[1]));
}
__device__ __forceinline__ void mma16(float c[4], const uint32_t a[4], const uint32_t b[2]) {
    asm volatile(
        "mma.sync.aligned.m16n8k16.row.col.f32.bf16.bf16.f32 "
        "{%0,%1,%2,%3},{%4,%5,%6,%7},{%8,%9},{%0,%1,%2,%3};"
        : "+f"(c[0]), "+f"(c[1]), "+f"(c[2]), "+f"(c[3])
        : "r"(a[0]), "r"(a[1]), "r"(a[2]), "r"(a[3]), "r"(b[0]), "r"(b[1]));
}
__device__ __forceinline__ void bsplit(float x, __nv_bfloat16& h, __nv_bfloat16& m) {
    h = __float2bfloat16(x);
    m = __float2bfloat16(x - __bfloat162float(h));
}
__device__ __forceinline__ uint32_t bpack(__nv_bfloat16 lo, __nv_bfloat16 hi) {
    __nv_bfloat162 t(lo, hi);
    return *reinterpret_cast<uint32_t*>(&t);
}
__device__ __forceinline__ uint32_t smem_u32(const void* p) {
    uint32_t a;
    asm("{ .reg .u64 t; cvta.to.shared.u64 t, %1; cvt.u32.u64 %0, t; }" : "=r"(a) : "l"(p));
    return a;
}
#define CP_ASYNC16(dst, src) \
    asm volatile("cp.async.cg.shared.global [%0], [%1], 16;" :: "r"(dst), "l"(src))
#define CP_COMMIT()  asm volatile("cp.async.commit_group;" ::: "memory")
#define CP_WAIT0()   asm volatile("cp.async.wait_group 0;" ::: "memory")

// ---------------- weight pack: bf16 hi/mid cells ------------------------------
// cell(ksg, q, n) = {hi(k=16ksg+2q, +1), hi(k=+2q+8, +9), mid(...), mid(...)}
// idx within matrix = (ksg*4 + q)*256 + n     (16384 cells / matrix)
__device__ __forceinline__ uint4 make_cell(const float* S, int stride,
                                           int ksg, int q, int n) {
    float x0 = S[(size_t)(16 * ksg + 2 * q)     * stride + n];
    float x1 = S[(size_t)(16 * ksg + 2 * q + 1) * stride + n];
    float x2 = S[(size_t)(16 * ksg + 2 * q + 8) * stride + n];
    float x3 = S[(size_t)(16 * ksg + 2 * q + 9) * stride + n];
    __nv_bfloat16 h0,m0,h1,m1,h2,m2,h3,m3;
    bsplit(x0,h0,m0); bsplit(x1,h1,m1); bsplit(x2,h2,m2); bsplit(x3,h3,m3);
    return make_uint4(bpack(h0,h1), bpack(h2,h3), bpack(m0,m1), bpack(m2,m3));
}
struct WTptrs { const float* src[16]; };
__global__ void pack_w(WTptrs p, uint4* __restrict__ dst) {
    int m = blockIdx.y;
    int c = blockIdx.x * 256 + threadIdx.x;      // 0..16383
    int n = c & 255, q = (c >> 8) & 3, ksg = c >> 10;
    dst[(size_t)m * 16384 + c] = make_cell(p.src[m], UU, ksg, q, n);
}
__global__ void pack_kv(const float* __restrict__ kv, uint4* __restrict__ dst) {
    int b = blockIdx.y;
    int c = blockIdx.x * 256 + threadIdx.x;
    int n = c & 255, q = (c >> 8) & 3, ksg = c >> 10;
    dst[(size_t)b * 16384 + c] = make_cell(kv + (size_t)b * UU * UU, UU, ksg, q, n);
}

// ---------------- CSR build: float4 + warp scan -------------------------------
__global__ void csr_build(const float* __restrict__ adj) {
    int r    = blockIdx.x * 8 + (threadIdx.x >> 5);
    int lane = threadIdx.x & 31;
    const float4* row = (const float4*)(adj + (size_t)r * NN);
    int base = 0;
    for (int c0 = 0; c0 < NN / 4; c0 += 32) {
        float4 v = row[c0 + lane];
        unsigned m4 = (v.x != 0.f ? 1u : 0u) | (v.y != 0.f ? 2u : 0u)
                    | (v.z != 0.f ? 4u : 0u) | (v.w != 0.f ? 8u : 0u);
        int cnt4 = __popc(m4);
        int inc = cnt4;
#pragma unroll
        for (int o = 1; o < 32; o <<= 1) {
            int t = __shfl_up_sync(0xffffffffu, inc, o);
            if (lane >= o) inc += t;
        }
        int pos = base + inc - cnt4;
        int colbase = (c0 + lane) * 4;
        if (m4 & 1) { if (pos < MAXNBR) g_cols[r * MAXNBR + pos] = colbase;     pos++; }
        if (m4 & 2) { if (pos < MAXNBR) g_cols[r * MAXNBR + pos] = colbase + 1; pos++; }
        if (m4 & 4) { if (pos < MAXNBR) g_cols[r * MAXNBR + pos] = colbase + 2; pos++; }
        if (m4 & 8) { if (pos < MAXNBR) g_cols[r * MAXNBR + pos] = colbase + 3; pos++; }
        base += __shfl_sync(0xffffffffu, inc, 31);
    }
    if (lane == 0) g_cnt[r] = base < MAXNBR ? base : MAXNBR;
}

// ---------------- spmm: adj @ x, float4, 4 rows/block -------------------------
__global__ void __launch_bounds__(256) spmm(const float* __restrict__ x,
                                            float* __restrict__ out, int rbase) {
    __shared__ int cols[4][MAXNBR];
    int sub = threadIdx.x >> 6;
    int t   = threadIdx.x & 63;
    int r      = rbase + blockIdx.x * 4 + sub;
    int rr     = r & (MROWS - 1);
    int stream = r >> 14;
    int cnt = g_cnt[rr];
    for (int i = t; i < cnt; i += 64) cols[sub][i] = g_cols[rr * MAXNBR + i];
    __syncthreads();
    const float* xb = x + ((size_t)stream * MROWS + (size_t)(rr & ~(NN - 1))) * UU;
    float4 s0 = {0,0,0,0}, s1 = {0,0,0,0};
    int j = 0;
    for (; j + 2 <= cnt; j += 2) {
        float4 v0 = *((const float4*)(xb + (size_t)cols[sub][j]     * UU) + t);
        float4 v1 = *((const float4*)(xb + (size_t)cols[sub][j + 1] * UU) + t);
        s0.x += v0.x; s0.y += v0.y; s0.z += v0.z; s0.w += v0.w;
        s1.x += v1.x; s1.y += v1.y; s1.z += v1.z; s1.w += v1.w;
    }
    if (j < cnt) {
        float4 v0 = *((const float4*)(xb + (size_t)cols[sub][j] * UU) + t);
        s0.x += v0.x; s0.y += v0.y; s0.z += v0.z; s0.w += v0.w;
    }
    float4 o = {s0.x + s1.x, s0.y + s1.y, s0.z + s1.z, s0.w + s1.w};
    *((float4*)(out + (size_t)r * UU) + t) = o;
}

// ---------------- 3xBF16 GEMM (hi/mid split), fragment-major smem -------------
// A cells: [2 ks16][4 q][128 r], q-stride 130, ks-stride 524 (uint4 units)
// B cells: [2 ks16][4 q][ 64 n], q-stride  66, ks-stride 264
struct GemmArgs {
    const float* A;
    const uint4* W0; const uint4* W1; const uint4* W2;   // packed bf16 weights
    const float* b0; const float* b1; const float* b2;
    float* C;
    const float* addsrc;
    const float* mask;
    const float* gamma; const float* beta; const float* mean; const float* var;
    int act0, act1, act2;
    int mm0, mm1, mm2;   // 0 none, 1 before act, 2 after act
    int ashared;
    int perBatchW;
};

#define A_Q  130
#define A_KS 524
#define B_Q  66
#define B_KS 264
#define SMEM_G ((2*A_KS + 2*B_KS) * (int)sizeof(uint4))   // 25,216 B

__global__ void __launch_bounds__(256, 2) gemm6(GemmArgs g) {
    extern __shared__ __align__(16) uint4 sm4[];
    uint4* Asm = sm4;                  // 2*A_KS
    uint4* Bsm = sm4 + 2 * A_KS;       // 2*B_KS

    int tid  = threadIdx.x;
    int lane = tid & 31;
    int wid  = tid >> 5;
    int wm   = wid & 3;
    int wn   = wid >> 2;
    int q    = lane & 3;
    int rg   = lane >> 2;
    int row0 = blockIdx.x * 128;
    int col0 = blockIdx.y * 64;
    int stream  = blockIdx.x >> 7;
    int rlocal0 = row0 - stream * MROWS;

    const uint4* W = (stream == 0) ? g.W0 : (stream == 1 ? g.W1 : g.W2);
    if (g.perBatchW) W = g.W0 + (size_t)(rlocal0 / NN) * 16384;
    const float* Arow = g.A + (size_t)(g.ashared ? rlocal0 : row0) * UU;

    int fA_ks = tid & 1, fA_r = tid >> 1;
    int fB_n  = tid & 63, fB_q = (tid >> 6) & 3;
    int aoff  = q * A_Q + wm * 32 + rg;
    int boff  = q * B_Q + wn * 32 + rg;

    float acc[2][4][4];
#pragma unroll
    for (int i = 0; i < 2; i++)
#pragma unroll
        for (int j = 0; j < 4; j++)
#pragma unroll
            for (int e = 0; e < 4; e++) acc[i][j][e] = 0.f;

    for (int k0 = 0; k0 < UU; k0 += 32) {
        if (k0) __syncthreads();

        // B tile: cp.async cells from packed weights
#pragma unroll
        for (int ksl = 0; ksl < 2; ksl++) {
            const uint4* src = W + (size_t)((k0 >> 4) + ksl) * 1024
                             + fB_q * 256 + col0 + fB_n;
            uint4* dst = Bsm + ksl * B_KS + fB_q * B_Q + fB_n;
            CP_ASYNC16(smem_u32(dst), src);
        }
        CP_COMMIT();

        // A tile: load 16 k floats per thread, split hi/mid, store 4 cells
        {
            const float4* s = (const float4*)(Arow + (size_t)fA_r * UU + k0 + fA_ks * 16);
            float4 v0 = s[0], v1 = s[1], v2 = s[2], v3 = s[3];
            float v[16] = {v0.x,v0.y,v0.z,v0.w, v1.x,v1.y,v1.z,v1.w,
                           v2.x,v2.y,v2.z,v2.w, v3.x,v3.y,v3.z,v3.w};
            __nv_bfloat16 h[16], m[16];
#pragma unroll
            for (int t = 0; t < 16; t++) bsplit(v[t], h[t], m[t]);
            uint4* ab = Asm + fA_ks * A_KS + fA_r;
#pragma unroll
            for (int qq = 0; qq < 4; qq++)
                ab[qq * A_Q] = make_uint4(
                    bpack(h[2*qq], h[2*qq+1]), bpack(h[2*qq+8], h[2*qq+9]),
                    bpack(m[2*qq], m[2*qq+1]), bpack(m[2*qq+8], m[2*qq+9]));
        }
        CP_WAIT0();
        __syncthreads();

#pragma unroll
        for (int ks = 0; ks < 2; ks++) {
            uint32_t ahi[2][4], amd[2][4];
            uint2 bhi[4], bmd[4];
            const uint4* ap = Asm + ks * A_KS + aoff;
            const uint4* bp = Bsm + ks * B_KS + boff;
#pragma unroll
            for (int i = 0; i < 2; i++) {
                uint4 c0 = ap[i * 16];       // row wm*32+i*16+rg
                uint4 c1 = ap[i * 16 + 8];   // row +8
                ahi[i][0] = c0.x; ahi[i][1] = c1.x; ahi[i][2] = c0.y; ahi[i][3] = c1.y;
                amd[i][0] = c0.z; amd[i][1] = c1.z; amd[i][2] = c0.w; amd[i][3] = c1.w;
            }
#pragma unroll
            for (int j = 0; j < 4; j++) {
                uint4 b = bp[j * 8];
                bhi[j] = make_uint2(b.x, b.y);
                bmd[j] = make_uint2(b.z, b.w);
            }
#pragma unroll
            for (int i = 0; i < 2; i++)
#pragma unroll
                for (int j = 0; j < 4; j++) {
                    uint32_t bh[2] = {bhi[j].x, bhi[j].y};
                    uint32_t bm[2] = {bmd[j].x, bmd[j].y};
                    mma16(acc[i][j], amd[i], bh);
                    mma16(acc[i][j], ahi[i], bm);
                    mma16(acc[i][j], ahi[i], bh);
                }
        }
    }

    const float* bias = (stream == 0) ? g.b0 : (stream == 1 ? g.b1 : g.b2);
    int act = (stream == 0) ? g.act0 : (stream == 1 ? g.act1 : g.act2);
    int mm  = (stream == 0) ? g.mm0  : (stream == 1 ? g.mm1  : g.mm2);

#pragma unroll
    for (int i = 0; i < 2; i++) {
#pragma unroll
        for (int p = 0; p < 2; p++) {
            int roff  = wm * 32 + i * 16 + rg + p * 8;
            int rglob = row0 + roff;
            int rloc  = rlocal0 + roff;
            float mk = mm ? g.mask[rloc] : 1.f;
#pragma unroll
            for (int j = 0; j < 4; j++) {
#pragma unroll
                for (int e = 0; e < 2; e++) {
                    int cc = col0 + wn * 32 + j * 8 + q * 2 + e;
                    float v = acc[i][j][p * 2 + e];
                    if (bias)     v += bias[cc];
                    if (g.addsrc) v += g.addsrc[(size_t)rglob * UU + cc];
                    if (g.gamma)
                        v = g.gamma[cc] * (v - g.mean[cc]) * rsqrtf(g.var[cc] + 1e-3f)
                            + g.beta[cc];
                    if (mm == 1) v *= mk;
                    if (act)     v *= 1.f / (1.f + __expf(-v));
                    if (mm == 2) v *= mk;
                    g.C[(size_t)rglob * UU + cc] = v;
                }
            }
        }
    }
}

// ---------------- kv[b][d][e] = sum_n pk[b,n,d] * pv[b,n,e] (3xTF32) ----------
__global__ void __launch_bounds__(256, 2) kv_t(const float* __restrict__ pk,
                                               const float* __restrict__ pv,
                                               float* __restrict__ kvout) {
    __shared__ float Ps[32][72];
    __shared__ float Vs[32][72];
    int tid  = threadIdx.x;
    int lane = tid & 31;
    int wid  = tid >> 5;
    int wm   = wid & 1;
    int wn   = wid >> 1;
    int d0 = blockIdx.x * 64, e0 = blockIdx.y * 64, b = blockIdx.z;
    const float* pkb = pk + (size_t)b * NN * UU;
    const float* pvb = pv + (size_t)b * NN * UU;

    float acc[2][2][4];
#pragma unroll
    for (int i = 0; i < 2; i++)
#pragma unroll
        for (int j = 0; j < 2; j++)
#pragma unroll
            for (int e = 0; e < 4; e++) acc[i][j][e] = 0.f;

    int q = lane & 3, rg = lane >> 2;

    for (int n0 = 0; n0 < NN; n0 += 32) {
#pragma unroll
        for (int i = 0; i < 2; i++) {
            int idx = tid + i * 256;
            int kr = idx >> 4, dc = (idx & 15) * 4;
            *(float4*)&Ps[kr][dc] = *(const float4*)(pkb + (size_t)(n0 + kr) * UU + d0 + dc);
            *(float4*)&Vs[kr][dc] = *(const float4*)(pvb + (size_t)(n0 + kr) * UU + e0 + dc);
        }
        __syncthreads();
#pragma unroll
        for (int ks = 0; ks < 4; ks++) {
            int kk = ks * 8;
            uint32_t ahi[2][4], alo[2][4], bhi[2][2], blo[2][2];
#pragma unroll
            for (int i = 0; i < 2; i++) {
                int rr = wm * 32 + i * 16 + rg;
                tsplit(Ps[kk + q    ][rr    ], ahi[i][0], alo[i][0]);
                tsplit(Ps[kk + q    ][rr + 8], ahi[i][1], alo[i][1]);
                tsplit(Ps[kk + q + 4][rr    ], ahi[i][2], alo[i][2]);
                tsplit(Ps[kk + q + 4][rr + 8], ahi[i][3], alo[i][3]);
            }
#pragma unroll
            for (int j = 0; j < 2; j++) {
                int nn = wn * 16 + j * 8 + rg;
                tsplit(Vs[kk + q    ][nn], bhi[j][0], blo[j][0]);
                tsplit(Vs[kk + q + 4][nn], bhi[j][1], blo[j][1]);
            }
#pragma unroll
            for (int i = 0; i < 2; i++)
#pragma unroll
                for (int j = 0; j < 2; j++) {
                    mma8(acc[i][j], alo[i], bhi[j]);
                    mma8(acc[i][j], ahi[i], blo[j]);
                    mma8(acc[i][j], ahi[i], bhi[j]);
                }
        }
        __syncthreads();
    }

    float* out = kvout + (size_t)b * UU * UU;
#pragma unroll
    for (int i = 0; i < 2; i++)
#pragma unroll
        for (int p = 0; p < 2; p++) {
            int dd = d0 + wm * 32 + i * 16 + rg + p * 8;
#pragma unroll
            for (int j = 0; j < 2; j++)
#pragma unroll
                for (int e = 0; e < 2; e++) {
                    int ee = e0 + wn * 16 + j * 8 + q * 2 + e;
                    out[(size_t)dd * UU + ee] = acc[i][j][p * 2 + e];
                }
        }
}

// ---------------- host orchestration -----------------------------------------
extern "C" void kernel_launch(void* const* d_in, const int* in_sizes, int n_in,
                              void* d_out, int out_size) {
    const float* x      = (const float*)d_in[0];
    const float* adj    = (const float*)d_in[1];
    const float* mask   = (const float*)d_in[2];
    const float* W_lin  = (const float*)d_in[3];
    const float* b_lin  = (const float*)d_in[4];
    const float* Wq_mp  = (const float*)d_in[5];
    const float* bq_mp  = (const float*)d_in[6];
    const float* Wk_mp  = (const float*)d_in[7];
    const float* bk_mp  = (const float*)d_in[8];
    const float* Wv_mp  = (const float*)d_in[9];
    const float* bv_mp  = (const float*)d_in[10];
    const float* Wk_att = (const float*)d_in[11];
    const float* Wv_att = (const float*)d_in[12];
    const float* Wq_att = (const float*)d_in[13];
    const float* Wo_att = (const float*)d_in[14];
    const float* gamma  = (const float*)d_in[15];
    const float* beta   = (const float*)d_in[16];
    const float* mean   = (const float*)d_in[17];
    const float* var    = (const float*)d_in[18];
    const float* W_proj = (const float*)d_in[19];
    const float* b_proj = (const float*)d_in[20];
    const float* W_res  = (const float*)d_in[21];
    const float* b_res  = (const float*)d_in[22];

    float *h, *y, *qkv, *t3, *kv;
    uint4 *kvp, *wp;
    cudaGetSymbolAddress((void**)&h,   g_h);
    cudaGetSymbolAddress((void**)&y,   g_y);
    cudaGetSymbolAddress((void**)&qkv, g_qkv);
    cudaGetSymbolAddress((void**)&t3,  g_t3);
    cudaGetSymbolAddress((void**)&kv,  g_kv);
    cudaGetSymbolAddress((void**)&kvp, g_kvp);
    cudaGetSymbolAddress((void**)&wp,  g_wp);

    const uint4* P_lin  = wp + 0  * 16384;
    const uint4* P_qmp  = wp + 1  * 16384;
    const uint4* P_kmp  = wp + 4  * 16384;
    const uint4* P_vmp  = wp + 7  * 16384;
    const uint4* P_katt = wp + 10 * 16384;
    const uint4* P_vatt = wp + 11 * 16384;
    const uint4* P_qatt = wp + 12 * 16384;
    const uint4* P_oatt = wp + 13 * 16384;
    const uint4* P_proj = wp + 14 * 16384;
    const uint4* P_res  = wp + 15 * 16384;

    {
        WTptrs p;
        p.src[0] = W_lin;
        p.src[1] = Wq_mp;  p.src[2] = Wq_mp + UU*UU;  p.src[3] = Wq_mp + 2*UU*UU;
        p.src[4] = Wk_mp;  p.src[5] = Wk_mp + UU*UU;  p.src[6] = Wk_mp + 2*UU*UU;
        p.src[7] = Wv_mp;  p.src[8] = Wv_mp + UU*UU;  p.src[9] = Wv_mp + 2*UU*UU;
        p.src[10] = Wk_att; p.src[11] = Wv_att; p.src[12] = Wq_att; p.src[13] = Wo_att;
        p.src[14] = W_proj; p.src[15] = W_res;
        pack_w<<<dim3(64, 16), 256>>>(p, wp);
    }

    cudaFuncSetAttribute(gemm6, cudaFuncAttributeMaxDynamicSharedMemorySize, SMEM_G);

    dim3 g1(MROWS / 128, UU / 64);       // 512 CTAs
    dim3 g3(3 * MROWS / 128, UU / 64);   // 1536 CTAs

    csr_build<<<MROWS / 8, 256>>>(adj);

    // h = x @ W_lin + b_lin
    { GemmArgs a = {}; a.A = x; a.W0 = P_lin; a.b0 = b_lin; a.C = h;
      gemm6<<<g1, 256, SMEM_G>>>(a); }

    // mp iteration 0: adj@h shared by all three streams
    // (split into two launches so ncu -s 5 lands on the g3 gemm below)
    spmm<<<MROWS / 8, 256>>>(h, t3, 0);
    spmm<<<MROWS / 8, 256>>>(h, t3, MROWS / 2);
    { GemmArgs a = {}; a.A = t3; a.ashared = 1;
      a.W0 = P_qmp; a.W1 = P_kmp; a.W2 = P_vmp;
      a.b0 = bq_mp; a.b1 = bk_mp; a.b2 = bv_mp;
      a.act0 = a.act1 = a.act2 = 1; a.C = qkv;
      gemm6<<<g3, 256, SMEM_G>>>(a); }

    // mp iterations 1..5
    for (int it = 1; it < 6; it++) {
        int i = it >> 1;
        spmm<<<3 * MROWS / 4, 256>>>(qkv, t3, 0);
        GemmArgs a = {}; a.A = t3;
        a.W0 = P_qmp + (size_t)i * 16384;
        a.W1 = P_kmp + (size_t)i * 16384;
        a.W2 = P_vmp + (size_t)i * 16384;
        a.b0 = bq_mp + i * UU; a.b1 = bk_mp + i * UU; a.b2 = bv_mp + i * UU;
        a.act0 = a.act1 = a.act2 = 1;
        if (it == 5) { a.mm0 = a.mm1 = a.mm2 = 2; a.mask = mask; }
        a.C = qkv;
        gemm6<<<g3, 256, SMEM_G>>>(a);
    }

    // attention projections: pq = q@Wq ; pk = silu((k@Wk)*m) ; pv = (v@Wv)*m
    { GemmArgs a = {}; a.A = qkv;
      a.W0 = P_qatt; a.W1 = P_katt; a.W2 = P_vatt;
      a.act1 = 1; a.mm1 = 1; a.mm2 = 1; a.mask = mask;
      a.C = t3;
      gemm6<<<g3, 256, SMEM_G>>>(a); }

    // kv[b] = pk^T @ pv  (float out), then pack to bf16 cells
    kv_t<<<dim3(UU / 64, UU / 64, BB), 256>>>(t3 + (size_t)MROWS * UU,
                                              t3 + (size_t)2 * MROWS * UU, kv);
    pack_kv<<<dim3(64, BB), 256>>>(kv, kvp);

    // attn = pq @ kv[b]
    { GemmArgs a = {}; a.A = t3; a.W0 = kvp; a.perBatchW = 1; a.C = h;
      gemm6<<<g1, 256, SMEM_G>>>(a); }

    // y = BN(attn @ Wo + x)
    { GemmArgs a = {}; a.A = h; a.W0 = P_oatt; a.addsrc = x;
      a.gamma = gamma; a.beta = beta; a.mean = mean; a.var = var; a.C = y;
      gemm6<<<g1, 256, SMEM_G>>>(a); }

    // p = silu(y @ W_proj + b_proj)
    { GemmArgs a = {}; a.A = y; a.W0 = P_proj; a.b0 = b_proj; a.act0 = 1; a.C = t3;
      gemm6<<<g1, 256, SMEM_G>>>(a); }

    // out = (p + x @ W_res + b_res) * mask
    { GemmArgs a = {}; a.A = x; a.W0 = P_res; a.b0 = b_res; a.addsrc = t3;
      a.mm0 = 2; a.mask = mask; a.C = (float*)d_out;
      gemm6<<<g1, 256, SMEM_G>>>(a); }
}

// round 14
// speedup vs baseline: 1.3679x; 1.0330x over previous
#include <cuda_runtime.h>
#include <cuda_bf16.h>
#include <cstdint>
#include <math.h>

#define BB 8
#define NN 2048
#define UU 256
#define MROWS (BB*NN)     // 16384
#define MAXNBR 128

// ---------------- device scratch ---------------------------------------------
__device__ float g_h  [MROWS*UU];
__device__ float g_y  [MROWS*UU];
__device__ float g_qkv[3*MROWS*UU];
__device__ float g_t3 [3*MROWS*UU];
__device__ float g_kv [BB*UU*UU];        // float kv / Mf per batch
__device__ uint4 g_kvp[BB*16384];        // packed bf16 cells (kv, then M)
__device__ uint4 g_wp [16*16384];        // packed bf16 weight cells (4MB)
__device__ int   g_cols[MROWS*MAXNBR];
__device__ int   g_cnt [MROWS];

// ---------------- helpers -----------------------------------------------------
__device__ __forceinline__ void tsplit(float x, uint32_t& hi, uint32_t& lo) {
    asm("cvt.rna.tf32.f32 %0, %1;" : "=r"(hi) : "f"(x));
    float r = x - __uint_as_float(hi);
    asm("cvt.rna.tf32.f32 %0, %1;" : "=r"(lo) : "f"(r));
}
__device__ __forceinline__ void mma8(float c[4], const uint32_t a[4], const uint32_t b[2]) {
    asm volatile(
        "mma.sync.aligned.m16n8k8.row.col.f32.tf32.tf32.f32 "
        "{%0,%1,%2,%3},{%4,%5,%6,%7},{%8,%9},{%0,%1,%2,%3};"
        : "+f"(c[0]), "+f"(c[1]), "+f"(c[2]), "+f"(c[3])
        : "r"(a[0]), "r"(a[1]), "r"(a[2]), "r"(a[3]), "r"(b[0]), "r"(b[1]));
}
__device__ __forceinline__ void mma16(float c[4], const uint32_t a[4], const uint32_t b[2]) {
    asm volatile(
        "mma.sync.aligned.m16n8k16.row.col.f32.bf16.bf16.f32 "
        "{%0,%1,%2,%3},{%4,%5,%6,%7},{%8,%9},{%0,%1,%2,%3};"
        : "+f"(c[0]), "+f"(c[1]), "+f"(c[2]), "+f"(c[3])
        : "r"(a[0]), "r"(a[1]), "r"(a[2]), "r"(a[3]), "r"(b[0]), "r"(b[1]));
}
__device__ __forceinline__ void bsplit(float x, __nv_bfloat16& h, __nv_bfloat16& m) {
    h = __float2bfloat16(x);
    m = __float2bfloat16(x - __bfloat162float(h));
}
__device__ __forceinline__ uint32_t bpack(__nv_bfloat16 lo, __nv_bfloat16 hi) {
    __nv_bfloat162 t(lo, hi);
    return *reinterpret_cast<uint32_t*>(&t);
}
__device__ __forceinline__ uint32_t smem_u32(const void* p) {
    uint32_t a;
    asm("{ .reg .u64 t; cvta.to.shared.u64 t, %1; cvt.u32.u64 %0, t; }" : "=r"(a) : "l"(p));
    return a;
}
#define CP_ASYNC16(dst, src) \
    asm volatile("cp.async.cg.shared.global [%0], [%1], 16;" :: "r"(dst), "l"(src))
#define CP_COMMIT()  asm volatile("cp.async.commit_group;" ::: "memory")
#define CP_WAIT0()   asm volatile("cp.async.wait_group 0;" ::: "memory")

// ---------------- bf16 cell pack ----------------------------------------------
// cell(ksg, q, n) = {hi(k=16ksg+2q, +1), hi(k=+2q+8, +9), mid(...), mid(...)}
__device__ __forceinline__ uint4 make_cell(const float* S, int stride,
                                           int ksg, int q, int n) {
    float x0 = S[(size_t)(16 * ksg + 2 * q)     * stride + n];
    float x1 = S[(size_t)(16 * ksg + 2 * q + 1) * stride + n];
    float x2 = S[(size_t)(16 * ksg + 2 * q + 8) * stride + n];
    float x3 = S[(size_t)(16 * ksg + 2 * q + 9) * stride + n];
    __nv_bfloat16 h0,m0,h1,m1,h2,m2,h3,m3;
    bsplit(x0,h0,m0); bsplit(x1,h1,m1); bsplit(x2,h2,m2); bsplit(x3,h3,m3);
    return make_uint4(bpack(h0,h1), bpack(h2,h3), bpack(m0,m1), bpack(m2,m3));
}
struct WTptrs { const float* src[16]; };
__global__ void pack_w(WTptrs p, uint4* __restrict__ dst) {
    int m = blockIdx.y;
    int c = blockIdx.x * 256 + threadIdx.x;      // 0..16383
    int n = c & 255, q = (c >> 8) & 3, ksg = c >> 10;
    dst[(size_t)m * 16384 + c] = make_cell(p.src[m], UU, ksg, q, n);
}
__global__ void pack_kv(const float* __restrict__ kv, uint4* __restrict__ dst) {
    int b = blockIdx.y;
    int c = blockIdx.x * 256 + threadIdx.x;
    int n = c & 255, q = (c >> 8) & 3, ksg = c >> 10;
    dst[(size_t)b * 16384 + c] = make_cell(kv + (size_t)b * UU * UU, UU, ksg, q, n);
}

// ---------------- CSR build: float4 + warp scan -------------------------------
__global__ void csr_build(const float* __restrict__ adj) {
    int r    = blockIdx.x * 8 + (threadIdx.x >> 5);
    int lane = threadIdx.x & 31;
    const float4* row = (const float4*)(adj + (size_t)r * NN);
    int base = 0;
    for (int c0 = 0; c0 < NN / 4; c0 += 32) {
        float4 v = row[c0 + lane];
        unsigned m4 = (v.x != 0.f ? 1u : 0u) | (v.y != 0.f ? 2u : 0u)
                    | (v.z != 0.f ? 4u : 0u) | (v.w != 0.f ? 8u : 0u);
        int cnt4 = __popc(m4);
        int inc = cnt4;
#pragma unroll
        for (int o = 1; o < 32; o <<= 1) {
            int t = __shfl_up_sync(0xffffffffu, inc, o);
            if (lane >= o) inc += t;
        }
        int pos = base + inc - cnt4;
        int colbase = (c0 + lane) * 4;
        if (m4 & 1) { if (pos < MAXNBR) g_cols[r * MAXNBR + pos] = colbase;     pos++; }
        if (m4 & 2) { if (pos < MAXNBR) g_cols[r * MAXNBR + pos] = colbase + 1; pos++; }
        if (m4 & 4) { if (pos < MAXNBR) g_cols[r * MAXNBR + pos] = colbase + 2; pos++; }
        if (m4 & 8) { if (pos < MAXNBR) g_cols[r * MAXNBR + pos] = colbase + 3; pos++; }
        base += __shfl_sync(0xffffffffu, inc, 31);
    }
    if (lane == 0) g_cnt[r] = base < MAXNBR ? base : MAXNBR;
}

// ---------------- spmm: adj @ x, float4, 4 rows/block -------------------------
__global__ void __launch_bounds__(256) spmm(const float* __restrict__ x,
                                            float* __restrict__ out) {
    __shared__ int cols[4][MAXNBR];
    int sub = threadIdx.x >> 6;
    int t   = threadIdx.x & 63;
    int r      = blockIdx.x * 4 + sub;
    int rr     = r & (MROWS - 1);
    int stream = r >> 14;
    int cnt = g_cnt[rr];
    for (int i = t; i < cnt; i += 64) cols[sub][i] = g_cols[rr * MAXNBR + i];
    __syncthreads();
    const float* xb = x + ((size_t)stream * MROWS + (size_t)(rr & ~(NN - 1))) * UU;
    float4 s0 = {0,0,0,0}, s1 = {0,0,0,0};
    int j = 0;
    for (; j + 2 <= cnt; j += 2) {
        float4 v0 = *((const float4*)(xb + (size_t)cols[sub][j]     * UU) + t);
        float4 v1 = *((const float4*)(xb + (size_t)cols[sub][j + 1] * UU) + t);
        s0.x += v0.x; s0.y += v0.y; s0.z += v0.z; s0.w += v0.w;
        s1.x += v1.x; s1.y += v1.y; s1.z += v1.z; s1.w += v1.w;
    }
    if (j < cnt) {
        float4 v0 = *((const float4*)(xb + (size_t)cols[sub][j] * UU) + t);
        s0.x += v0.x; s0.y += v0.y; s0.z += v0.z; s0.w += v0.w;
    }
    float4 o = {s0.x + s1.x, s0.y + s1.y, s0.z + s1.z, s0.w + s1.w};
    *((float4*)(out + (size_t)r * UU) + t) = o;
}

// ---------------- 3xBF16 GEMM (hi/mid split), fragment-major smem -------------
struct GemmArgs {
    const float* A;
    const uint4* W0; const uint4* W1; const uint4* W2;   // packed bf16 weights
    const float* b0; const float* b1; const float* b2;
    float* C;
    const float* addsrc;
    const float* mask;
    const float* gamma; const float* beta; const float* mean; const float* var;
    int act0, act1, act2;
    int mm0, mm1, mm2;   // 0 none, 1 before act, 2 after act
    int ashared;         // A row = rlocal0 (stream-shared A)
    int amod;            // if >0: A row = rlocal0 % amod
    int wdiv;            // if >0: W = W0 + (rlocal0/wdiv)*16384
};

#define A_Q  130
#define A_KS 524
#define B_Q  66
#define B_KS 264
#define SMEM_G ((2*A_KS + 2*B_KS) * (int)sizeof(uint4))   // 25,216 B

__global__ void __launch_bounds__(256, 2) gemm6(GemmArgs g) {
    extern __shared__ __align__(16) uint4 sm4[];
    uint4* Asm = sm4;
    uint4* Bsm = sm4 + 2 * A_KS;

    int tid  = threadIdx.x;
    int lane = tid & 31;
    int wid  = tid >> 5;
    int wm   = wid & 3;
    int wn   = wid >> 2;
    int q    = lane & 3;
    int rg   = lane >> 2;
    int row0 = blockIdx.x * 128;
    int col0 = blockIdx.y * 64;
    int stream  = blockIdx.x >> 7;
    int rlocal0 = row0 - stream * MROWS;

    const uint4* W = (stream == 0) ? g.W0 : (stream == 1 ? g.W1 : g.W2);
    if (g.wdiv) W = g.W0 + (size_t)(rlocal0 / g.wdiv) * 16384;
    int arow0 = g.amod ? (rlocal0 % g.amod) : (g.ashared ? rlocal0 : row0);
    const float* Arow = g.A + (size_t)arow0 * UU;

    int fA_ks = tid & 1, fA_r = tid >> 1;
    int fB_n  = tid & 63, fB_q = (tid >> 6) & 3;
    int aoff  = q * A_Q + wm * 32 + rg;
    int boff  = q * B_Q + wn * 32 + rg;

    float acc[2][4][4];
#pragma unroll
    for (int i = 0; i < 2; i++)
#pragma unroll
        for (int j = 0; j < 4; j++)
#pragma unroll
            for (int e = 0; e < 4; e++) acc[i][j][e] = 0.f;

    for (int k0 = 0; k0 < UU; k0 += 32) {
        if (k0) __syncthreads();

#pragma unroll
        for (int ksl = 0; ksl < 2; ksl++) {
            const uint4* src = W + (size_t)((k0 >> 4) + ksl) * 1024
                             + fB_q * 256 + col0 + fB_n;
            uint4* dst = Bsm + ksl * B_KS + fB_q * B_Q + fB_n;
            CP_ASYNC16(smem_u32(dst), src);
        }
        CP_COMMIT();

        {
            const float4* s = (const float4*)(Arow + (size_t)fA_r * UU + k0 + fA_ks * 16);
            float4 v0 = s[0], v1 = s[1], v2 = s[2], v3 = s[3];
            float v[16] = {v0.x,v0.y,v0.z,v0.w, v1.x,v1.y,v1.z,v1.w,
                           v2.x,v2.y,v2.z,v2.w, v3.x,v3.y,v3.z,v3.w};
            __nv_bfloat16 h[16], m[16];
#pragma unroll
            for (int t = 0; t < 16; t++) bsplit(v[t], h[t], m[t]);
            uint4* ab = Asm + fA_ks * A_KS + fA_r;
#pragma unroll
            for (int qq = 0; qq < 4; qq++)
                ab[qq * A_Q] = make_uint4(
                    bpack(h[2*qq], h[2*qq+1]), bpack(h[2*qq+8], h[2*qq+9]),
                    bpack(m[2*qq], m[2*qq+1]), bpack(m[2*qq+8], m[2*qq+9]));
        }
        CP_WAIT0();
        __syncthreads();

#pragma unroll
        for (int ks = 0; ks < 2; ks++) {
            uint32_t ahi[2][4], amd[2][4];
            uint2 bhi[4], bmd[4];
            const uint4* ap = Asm + ks * A_KS + aoff;
            const uint4* bp = Bsm + ks * B_KS + boff;
#pragma unroll
            for (int i = 0; i < 2; i++) {
                uint4 c0 = ap[i * 16];
                uint4 c1 = ap[i * 16 + 8];
                ahi[i][0] = c0.x; ahi[i][1] = c1.x; ahi[i][2] = c0.y; ahi[i][3] = c1.y;
                amd[i][0] = c0.z; amd[i][1] = c1.z; amd[i][2] = c0.w; amd[i][3] = c1.w;
            }
#pragma unroll
            for (int j = 0; j < 4; j++) {
                uint4 b = bp[j * 8];
                bhi[j] = make_uint2(b.x, b.y);
                bmd[j] = make_uint2(b.z, b.w);
            }
#pragma unroll
            for (int i = 0; i < 2; i++)
#pragma unroll
                for (int j = 0; j < 4; j++) {
                    uint32_t bh[2] = {bhi[j].x, bhi[j].y};
                    uint32_t bm[2] = {bmd[j].x, bmd[j].y};
                    mma16(acc[i][j], amd[i], bh);
                    mma16(acc[i][j], ahi[i], bm);
                    mma16(acc[i][j], ahi[i], bh);
                }
        }
    }

    const float* bias = (stream == 0) ? g.b0 : (stream == 1 ? g.b1 : g.b2);
    int act = (stream == 0) ? g.act0 : (stream == 1 ? g.act1 : g.act2);
    int mm  = (stream == 0) ? g.mm0  : (stream == 1 ? g.mm1  : g.mm2);

#pragma unroll
    for (int i = 0; i < 2; i++) {
#pragma unroll
        for (int p = 0; p < 2; p++) {
            int roff  = wm * 32 + i * 16 + rg + p * 8;
            int rglob = row0 + roff;
            int rloc  = rlocal0 + roff;
            float mk = mm ? g.mask[rloc] : 1.f;
#pragma unroll
            for (int j = 0; j < 4; j++) {
#pragma unroll
                for (int e = 0; e < 2; e++) {
                    int cc = col0 + wn * 32 + j * 8 + q * 2 + e;
                    float v = acc[i][j][p * 2 + e];
                    if (bias)     v += bias[cc];
                    if (g.addsrc) v += g.addsrc[(size_t)rglob * UU + cc];
                    if (g.gamma)
                        v = g.gamma[cc] * (v - g.mean[cc]) * rsqrtf(g.var[cc] + 1e-3f)
                            + g.beta[cc];
                    if (mm == 1) v *= mk;
                    if (act)     v *= 1.f / (1.f + __expf(-v));
                    if (mm == 2) v *= mk;
                    g.C[(size_t)rglob * UU + cc] = v;
                }
            }
        }
    }
}

// ---------------- kv[b][d][e] = sum_n pk[b,n,d] * pv[b,n,e] (3xTF32) ----------
__global__ void __launch_bounds__(256, 2) kv_t(const float* __restrict__ pk,
                                               const float* __restrict__ pv,
                                               float* __restrict__ kvout) {
    __shared__ float Ps[32][72];
    __shared__ float Vs[32][72];
    int tid  = threadIdx.x;
    int lane = tid & 31;
    int wid  = tid >> 5;
    int wm   = wid & 1;
    int wn   = wid >> 1;
    int d0 = blockIdx.x * 64, e0 = blockIdx.y * 64, b = blockIdx.z;
    const float* pkb = pk + (size_t)b * NN * UU;
    const float* pvb = pv + (size_t)b * NN * UU;

    float acc[2][2][4];
#pragma unroll
    for (int i = 0; i < 2; i++)
#pragma unroll
        for (int j = 0; j < 2; j++)
#pragma unroll
            for (int e = 0; e < 4; e++) acc[i][j][e] = 0.f;

    int q = lane & 3, rg = lane >> 2;

    for (int n0 = 0; n0 < NN; n0 += 32) {
#pragma unroll
        for (int i = 0; i < 2; i++) {
            int idx = tid + i * 256;
            int kr = idx >> 4, dc = (idx & 15) * 4;
            *(float4*)&Ps[kr][dc] = *(const float4*)(pkb + (size_t)(n0 + kr) * UU + d0 + dc);
            *(float4*)&Vs[kr][dc] = *(const float4*)(pvb + (size_t)(n0 + kr) * UU + e0 + dc);
        }
        __syncthreads();
#pragma unroll
        for (int ks = 0; ks < 4; ks++) {
            int kk = ks * 8;
            uint32_t ahi[2][4], alo[2][4], bhi[2][2], blo[2][2];
#pragma unroll
            for (int i = 0; i < 2; i++) {
                int rr = wm * 32 + i * 16 + rg;
                tsplit(Ps[kk + q    ][rr    ], ahi[i][0], alo[i][0]);
                tsplit(Ps[kk + q    ][rr + 8], ahi[i][1], alo[i][1]);
                tsplit(Ps[kk + q + 4][rr    ], ahi[i][2], alo[i][2]);
                tsplit(Ps[kk + q + 4][rr + 8], ahi[i][3], alo[i][3]);
            }
#pragma unroll
            for (int j = 0; j < 2; j++) {
                int nn = wn * 16 + j * 8 + rg;
                tsplit(Vs[kk + q    ][nn], bhi[j][0], blo[j][0]);
                tsplit(Vs[kk + q + 4][nn], bhi[j][1], blo[j][1]);
            }
#pragma unroll
            for (int i = 0; i < 2; i++)
#pragma unroll
                for (int j = 0; j < 2; j++) {
                    mma8(acc[i][j], alo[i], bhi[j]);
                    mma8(acc[i][j], ahi[i], blo[j]);
                    mma8(acc[i][j], ahi[i], bhi[j]);
                }
        }
        __syncthreads();
    }

    float* out = kvout + (size_t)b * UU * UU;
#pragma unroll
    for (int i = 0; i < 2; i++)
#pragma unroll
        for (int p = 0; p < 2; p++) {
            int dd = d0 + wm * 32 + i * 16 + rg + p * 8;
#pragma unroll
            for (int j = 0; j < 2; j++)
#pragma unroll
                for (int e = 0; e < 2; e++) {
                    int ee = e0 + wn * 16 + j * 8 + q * 2 + e;
                    out[(size_t)dd * UU + ee] = acc[i][j][p * 2 + e];
                }
        }
}

// ---------------- host orchestration -----------------------------------------
extern "C" void kernel_launch(void* const* d_in, const int* in_sizes, int n_in,
                              void* d_out, int out_size) {
    const float* x      = (const float*)d_in[0];
    const float* adj    = (const float*)d_in[1];
    const float* mask   = (const float*)d_in[2];
    const float* W_lin  = (const float*)d_in[3];
    const float* b_lin  = (const float*)d_in[4];
    const float* Wq_mp  = (const float*)d_in[5];
    const float* bq_mp  = (const float*)d_in[6];
    const float* Wk_mp  = (const float*)d_in[7];
    const float* bk_mp  = (const float*)d_in[8];
    const float* Wv_mp  = (const float*)d_in[9];
    const float* bv_mp  = (const float*)d_in[10];
    const float* Wk_att = (const float*)d_in[11];
    const float* Wv_att = (const float*)d_in[12];
    const float* Wq_att = (const float*)d_in[13];
    const float* Wo_att = (const float*)d_in[14];
    const float* gamma  = (const float*)d_in[15];
    const float* beta   = (const float*)d_in[16];
    const float* mean   = (const float*)d_in[17];
    const float* var    = (const float*)d_in[18];
    const float* W_proj = (const float*)d_in[19];
    const float* b_proj = (const float*)d_in[20];
    const float* W_res  = (const float*)d_in[21];
    const float* b_res  = (const float*)d_in[22];

    float *h, *y, *qkv, *t3, *kv;
    uint4 *kvp, *wp;
    cudaGetSymbolAddress((void**)&h,   g_h);
    cudaGetSymbolAddress((void**)&y,   g_y);
    cudaGetSymbolAddress((void**)&qkv, g_qkv);
    cudaGetSymbolAddress((void**)&t3,  g_t3);
    cudaGetSymbolAddress((void**)&kv,  g_kv);
    cudaGetSymbolAddress((void**)&kvp, g_kvp);
    cudaGetSymbolAddress((void**)&wp,  g_wp);

    const uint4* P_lin  = wp + 0  * 16384;
    const uint4* P_qmp  = wp + 1  * 16384;
    const uint4* P_kmp  = wp + 4  * 16384;
    const uint4* P_vmp  = wp + 7  * 16384;
    const uint4* P_katt = wp + 10 * 16384;
    const uint4* P_vatt = wp + 11 * 16384;
    const uint4* P_oatt = wp + 13 * 16384;
    const uint4* P_proj = wp + 14 * 16384;
    const uint4* P_res  = wp + 15 * 16384;

    {
        WTptrs p;
        p.src[0] = W_lin;
        p.src[1] = Wq_mp;  p.src[2] = Wq_mp + UU*UU;  p.src[3] = Wq_mp + 2*UU*UU;
        p.src[4] = Wk_mp;  p.src[5] = Wk_mp + UU*UU;  p.src[6] = Wk_mp + 2*UU*UU;
        p.src[7] = Wv_mp;  p.src[8] = Wv_mp + UU*UU;  p.src[9] = Wv_mp + 2*UU*UU;
        p.src[10] = Wk_att; p.src[11] = Wv_att; p.src[12] = Wq_att; p.src[13] = Wo_att;
        p.src[14] = W_proj; p.src[15] = W_res;
        pack_w<<<dim3(64, 16), 256>>>(p, wp);
    }

    cudaFuncSetAttribute(gemm6, cudaFuncAttributeMaxDynamicSharedMemorySize, SMEM_G);

    dim3 g1(MROWS / 128, UU / 64);         // 512 CTAs
    dim3 g2(2 * MROWS / 128, UU / 64);     // 1024 CTAs
    dim3 g3(3 * MROWS / 128, UU / 64);     // 1536 CTAs
    dim3 gS(2048 / 128, UU / 64);          // 64 CTAs (small batched gemms)

    csr_build<<<MROWS / 8, 256>>>(adj);

    // h = x @ W_lin + b_lin
    { GemmArgs a = {}; a.A = x; a.W0 = P_lin; a.b0 = b_lin; a.C = h;
      gemm6<<<g1, 256, SMEM_G>>>(a); }

    // mp iteration 0: adj@h shared by all three streams
    spmm<<<MROWS / 4, 256>>>(h, t3);
    { GemmArgs a = {}; a.A = t3; a.ashared = 1;
      a.W0 = P_qmp; a.W1 = P_kmp; a.W2 = P_vmp;
      a.b0 = bq_mp; a.b1 = bk_mp; a.b2 = bv_mp;
      a.act0 = a.act1 = a.act2 = 1; a.C = qkv;
      gemm6<<<g3, 256, SMEM_G>>>(a); }

    // mp iterations 1..5
    for (int it = 1; it < 6; it++) {
        int i = it >> 1;
        spmm<<<3 * MROWS / 4, 256>>>(qkv, t3);
        GemmArgs a = {}; a.A = t3;
        a.W0 = P_qmp + (size_t)i * 16384;
        a.W1 = P_kmp + (size_t)i * 16384;
        a.W2 = P_vmp + (size_t)i * 16384;
        a.b0 = bq_mp + i * UU; a.b1 = bk_mp + i * UU; a.b2 = bv_mp + i * UU;
        a.act0 = a.act1 = a.act2 = 1;
        if (it == 5) { a.mm0 = a.mm1 = a.mm2 = 2; a.mask = mask; }
        a.C = qkv;
        gemm6<<<g3, 256, SMEM_G>>>(a);
    }

    // attention projections (k, v only): pk = silu((k@Wk)*m) ; pv = (v@Wv)*m
    { GemmArgs a = {}; a.A = qkv + (size_t)MROWS * UU;
      a.W0 = P_katt; a.W1 = P_vatt;
      a.act0 = 1; a.mm0 = 1; a.mm1 = 1; a.mask = mask;
      a.C = t3 + (size_t)MROWS * UU;
      gemm6<<<g2, 256, SMEM_G>>>(a); }

    // kv[b] = pk^T @ pv  (float), pack to bf16 cells
    kv_t<<<dim3(UU / 64, UU / 64, BB), 256>>>(t3 + (size_t)MROWS * UU,
                                              t3 + (size_t)2 * MROWS * UU, kv);
    pack_kv<<<dim3(64, BB), 256>>>(kv, kvp);

    // T1[b] = Wq_att @ kv[b]   (rows = 8*256, A row = row%256, W per 256 rows)
    { GemmArgs a = {}; a.A = Wq_att; a.amod = UU; a.W0 = kvp; a.wdiv = UU; a.C = h;
      gemm6<<<gS, 256, SMEM_G>>>(a); }

    // M[b] = T1[b] @ Wo
    { GemmArgs a = {}; a.A = h; a.W0 = P_oatt; a.C = kv;
      gemm6<<<gS, 256, SMEM_G>>>(a); }
    pack_kv<<<dim3(64, BB), 256>>>(kv, kvp);

    // y = BN(q @ M[b] + x)
    { GemmArgs a = {}; a.A = qkv; a.W0 = kvp; a.wdiv = NN; a.addsrc = x;
      a.gamma = gamma; a.beta = beta; a.mean = mean; a.var = var; a.C = y;
      gemm6<<<g1, 256, SMEM_G>>>(a); }

    // p = silu(y @ W_proj + b_proj)
    { GemmArgs a = {}; a.A = y; a.W0 = P_proj; a.b0 = b_proj; a.act0 = 1; a.C = t3;
      gemm6<<<g1, 256, SMEM_G>>>(a); }

    // out = (p + x @ W_res + b_res) * mask
    { GemmArgs a = {}; a.A = x; a.W0 = P_res; a.b0 = b_res; a.addsrc = t3;
      a.mm0 = 2; a.mask = mask; a.C = (float*)d_out;
      gemm6<<<g1, 256, SMEM_G>>>(a); }
}

// round 15
// speedup vs baseline: 1.3766x; 1.0063x over previous
#include <cuda_runtime.h>
#include <cuda_bf16.h>
#include <cstdint>
#include <math.h>

#define BB 8
#define NN 2048
#define UU 256
#define MROWS (BB*NN)     // 16384
#define MAXNBR 128

// ---------------- device scratch ---------------------------------------------
__device__ float g_h  [MROWS*UU];        // scratch (T1 in attention tail)
__device__ float g_y  [MROWS*UU];
__device__ float g_qkv[3*MROWS*UU];
__device__ float g_t3 [3*MROWS*UU];
__device__ float g_kv [BB*UU*UU];        // float kv / M per batch
__device__ uint4 g_kvp[BB*16384];        // packed bf16 cells (kv, then M)
__device__ uint4 g_wp [19*16384];        // packed bf16 weight cells (16 + 3 fused)
__device__ float g_bvec[3*UU];           // b_lin @ (W_lin@W*_mp0)
__device__ float g_deg[MROWS];           // adjacency row sums
__device__ int   g_cols[MROWS*MAXNBR];
__device__ int   g_cnt [MROWS];

// ---------------- helpers -----------------------------------------------------
__device__ __forceinline__ void tsplit(float x, uint32_t& hi, uint32_t& lo) {
    asm("cvt.rna.tf32.f32 %0, %1;" : "=r"(hi) : "f"(x));
    float r = x - __uint_as_float(hi);
    asm("cvt.rna.tf32.f32 %0, %1;" : "=r"(lo) : "f"(r));
}
__device__ __forceinline__ void mma8(float c[4], const uint32_t a[4], const uint32_t b[2]) {
    asm volatile(
        "mma.sync.aligned.m16n8k8.row.col.f32.tf32.tf32.f32 "
        "{%0,%1,%2,%3},{%4,%5,%6,%7},{%8,%9},{%0,%1,%2,%3};"
        : "+f"(c[0]), "+f"(c[1]), "+f"(c[2]), "+f"(c[3])
        : "r"(a[0]), "r"(a[1]), "r"(a[2]), "r"(a[3]), "r"(b[0]), "r"(b[1]));
}
__device__ __forceinline__ void mma16(float c[4], const uint32_t a[4], const uint32_t b[2]) {
    asm volatile(
        "mma.sync.aligned.m16n8k16.row.col.f32.bf16.bf16.f32 "
        "{%0,%1,%2,%3},{%4,%5,%6,%7},{%8,%9},{%0,%1,%2,%3};"
        : "+f"(c[0]), "+f"(c[1]), "+f"(c[2]), "+f"(c[3])
        : "r"(a[0]), "r"(a[1]), "r"(a[2]), "r"(a[3]), "r"(b[0]), "r"(b[1]));
}
__device__ __forceinline__ void bsplit(float x, __nv_bfloat16& h, __nv_bfloat16& m) {
    h = __float2bfloat16(x);
    m = __float2bfloat16(x - __bfloat162float(h));
}
__device__ __forceinline__ uint32_t bpack(__nv_bfloat16 lo, __nv_bfloat16 hi) {
    __nv_bfloat162 t(lo, hi);
    return *reinterpret_cast<uint32_t*>(&t);
}
__device__ __forceinline__ uint32_t smem_u32(const void* p) {
    uint32_t a;
    asm("{ .reg .u64 t; cvta.to.shared.u64 t, %1; cvt.u32.u64 %0, t; }" : "=r"(a) : "l"(p));
    return a;
}
#define CP_ASYNC16(dst, src) \
    asm volatile("cp.async.cg.shared.global [%0], [%1], 16;" :: "r"(dst), "l"(src))
#define CP_COMMIT()  asm volatile("cp.async.commit_group;" ::: "memory")
#define CP_WAIT0()   asm volatile("cp.async.wait_group 0;" ::: "memory")

// ---------------- bf16 cell helpers -------------------------------------------
__device__ __forceinline__ uint4 vals_to_cell(float x0, float x1, float x2, float x3) {
    __nv_bfloat16 h0,m0,h1,m1,h2,m2,h3,m3;
    bsplit(x0,h0,m0); bsplit(x1,h1,m1); bsplit(x2,h2,m2); bsplit(x3,h3,m3);
    return make_uint4(bpack(h0,h1), bpack(h2,h3), bpack(m0,m1), bpack(m2,m3));
}
__device__ __forceinline__ uint4 make_cell(const float* S, int stride,
                                           int ksg, int q, int n) {
    float x0 = S[(size_t)(16 * ksg + 2 * q)     * stride + n];
    float x1 = S[(size_t)(16 * ksg + 2 * q + 1) * stride + n];
    float x2 = S[(size_t)(16 * ksg + 2 * q + 8) * stride + n];
    float x3 = S[(size_t)(16 * ksg + 2 * q + 9) * stride + n];
    return vals_to_cell(x0, x1, x2, x3);
}

// ---------------- packall: weights + fused W_lin@W*_mp0 + bvec ----------------
// y<16: plain pack of matrix y.  y in 16..18: product pack W_lin @ p.src[1+3s].
// y in 19..21 (blockIdx.x==0): bvec[s] = b_lin @ (W_lin@W*_mp0)  (= (b_lin@W_lin')... )
struct WTptrs { const float* src[16]; };
__global__ void packall(WTptrs p, uint4* __restrict__ dst,
                        float* __restrict__ bvec, const float* __restrict__ b_lin) {
    int y = blockIdx.y;
    if (y < 16) {
        int c = blockIdx.x * 256 + threadIdx.x;
        int n = c & 255, q = (c >> 8) & 3, ksg = c >> 10;
        dst[(size_t)y * 16384 + c] = make_cell(p.src[y], UU, ksg, q, n);
        return;
    }
    if (y < 19) {
        __shared__ float wl[4][UU];
        int s = y - 16;
        const float* Wlin = p.src[0];
        const float* B    = p.src[1 + 3 * s];
        int c = blockIdx.x * 256 + threadIdx.x;
        int n = c & 255, q = (c >> 8) & 3, ksg = c >> 10;
        int k0 = 16 * ksg + 2 * q;
        int kk[4] = {k0, k0 + 1, k0 + 8, k0 + 9};
#pragma unroll
        for (int r = 0; r < 4; r++)
            wl[r][threadIdx.x] = Wlin[(size_t)kk[r] * UU + threadIdx.x];
        __syncthreads();
        float a0 = 0.f, a1 = 0.f, a2 = 0.f, a3 = 0.f;
        for (int m = 0; m < UU; m++) {
            float bm = B[(size_t)m * UU + n];
            a0 += wl[0][m] * bm; a1 += wl[1][m] * bm;
            a2 += wl[2][m] * bm; a3 += wl[3][m] * bm;
        }
        dst[(size_t)y * 16384 + c] = vals_to_cell(a0, a1, a2, a3);
        return;
    }
    // bvec
    if (blockIdx.x == 0) {
        int s = y - 19;
        const float* Wlin = p.src[0];
        const float* B    = p.src[1 + 3 * s];
        int n = threadIdx.x;
        // bvec_s[n] = sum_k b_lin[k] * (Wlin@B)[k][n] = sum_m (b_lin@Wlin)[m] * B[m][n]
        float acc = 0.f;
        for (int m = 0; m < UU; m++) {
            float t = 0.f;
            // t = (b_lin @ Wlin)[m] -- recompute per m is O(U^2); hoist instead:
            t = 0.f;
            (void)t;
            acc += 0.f;  // placeholder, replaced below
        }
        // compute via two stages in registers/smem
        __shared__ float bw[UU];   // b_lin @ Wlin
        float a = 0.f;
        for (int k = 0; k < UU; k++) a += b_lin[k] * Wlin[(size_t)k * UU + n];
        bw[n] = a;
        __syncthreads();
        acc = 0.f;
        for (int m = 0; m < UU; m++) acc += bw[m] * B[(size_t)m * UU + n];
        bvec[s * UU + n] = acc;
    }
}

// ---------------- CSR build: float4 + warp scan + row degree ------------------
__global__ void csr_build(const float* __restrict__ adj) {
    int r    = blockIdx.x * 8 + (threadIdx.x >> 5);
    int lane = threadIdx.x & 31;
    const float4* row = (const float4*)(adj + (size_t)r * NN);
    int base = 0;
    for (int c0 = 0; c0 < NN / 4; c0 += 32) {
        float4 v = row[c0 + lane];
        unsigned m4 = (v.x != 0.f ? 1u : 0u) | (v.y != 0.f ? 2u : 0u)
                    | (v.z != 0.f ? 4u : 0u) | (v.w != 0.f ? 8u : 0u);
        int cnt4 = __popc(m4);
        int inc = cnt4;
#pragma unroll
        for (int o = 1; o < 32; o <<= 1) {
            int t = __shfl_up_sync(0xffffffffu, inc, o);
            if (lane >= o) inc += t;
        }
        int pos = base + inc - cnt4;
        int colbase = (c0 + lane) * 4;
        if (m4 & 1) { if (pos < MAXNBR) g_cols[r * MAXNBR + pos] = colbase;     pos++; }
        if (m4 & 2) { if (pos < MAXNBR) g_cols[r * MAXNBR + pos] = colbase + 1; pos++; }
        if (m4 & 4) { if (pos < MAXNBR) g_cols[r * MAXNBR + pos] = colbase + 2; pos++; }
        if (m4 & 8) { if (pos < MAXNBR) g_cols[r * MAXNBR + pos] = colbase + 3; pos++; }
        base += __shfl_sync(0xffffffffu, inc, 31);
    }
    if (lane == 0) {
        g_cnt[r] = base < MAXNBR ? base : MAXNBR;
        g_deg[r] = (float)base;
    }
}

// ---------------- spmm: adj @ x, float4, 4 rows/block -------------------------
__global__ void __launch_bounds__(256) spmm(const float* __restrict__ x,
                                            float* __restrict__ out) {
    __shared__ int cols[4][MAXNBR];
    int sub = threadIdx.x >> 6;
    int t   = threadIdx.x & 63;
    int r      = blockIdx.x * 4 + sub;
    int rr     = r & (MROWS - 1);
    int stream = r >> 14;
    int cnt = g_cnt[rr];
    for (int i = t; i < cnt; i += 64) cols[sub][i] = g_cols[rr * MAXNBR + i];
    __syncthreads();
    const float* xb = x + ((size_t)stream * MROWS + (size_t)(rr & ~(NN - 1))) * UU;
    float4 s0 = {0,0,0,0}, s1 = {0,0,0,0};
    int j = 0;
    for (; j + 2 <= cnt; j += 2) {
        float4 v0 = *((const float4*)(xb + (size_t)cols[sub][j]     * UU) + t);
        float4 v1 = *((const float4*)(xb + (size_t)cols[sub][j + 1] * UU) + t);
        s0.x += v0.x; s0.y += v0.y; s0.z += v0.z; s0.w += v0.w;
        s1.x += v1.x; s1.y += v1.y; s1.z += v1.z; s1.w += v1.w;
    }
    if (j < cnt) {
        float4 v0 = *((const float4*)(xb + (size_t)cols[sub][j] * UU) + t);
        s0.x += v0.x; s0.y += v0.y; s0.z += v0.z; s0.w += v0.w;
    }
    float4 o = {s0.x + s1.x, s0.y + s1.y, s0.z + s1.z, s0.w + s1.w};
    *((float4*)(out + (size_t)r * UU) + t) = o;
}

// ---------------- 3xBF16 GEMM (hi/mid split), fragment-major smem -------------
struct GemmArgs {
    const float* A;
    const uint4* W0; const uint4* W1; const uint4* W2;
    const float* b0; const float* b1; const float* b2;
    float* C;
    const float* addsrc;
    const float* mask;
    const float* gamma; const float* beta; const float* mean; const float* var;
    const float* deg;                       // per-row scale for rank-1 bias
    const float* rb0; const float* rb1; const float* rb2;  // rank-1 bias vectors
    int act0, act1, act2;
    int mm0, mm1, mm2;   // 0 none, 1 before act, 2 after act
    int ashared;         // A row = rlocal0
    int amod;            // if >0: A row = rlocal0 % amod
    int wdiv;            // if >0: W = W0 + (rlocal0/wdiv)*16384
};

#define A_Q  130
#define A_KS 524
#define B_Q  66
#define B_KS 264
#define SMEM_G ((2*A_KS + 2*B_KS) * (int)sizeof(uint4))   // 25,216 B

__global__ void __launch_bounds__(256, 2) gemm6(GemmArgs g) {
    extern __shared__ __align__(16) uint4 sm4[];
    uint4* Asm = sm4;
    uint4* Bsm = sm4 + 2 * A_KS;

    int tid  = threadIdx.x;
    int lane = tid & 31;
    int wid  = tid >> 5;
    int wm   = wid & 3;
    int wn   = wid >> 2;
    int q    = lane & 3;
    int rg   = lane >> 2;
    int row0 = blockIdx.x * 128;
    int col0 = blockIdx.y * 64;
    int stream  = blockIdx.x >> 7;
    int rlocal0 = row0 - stream * MROWS;

    const uint4* W = (stream == 0) ? g.W0 : (stream == 1 ? g.W1 : g.W2);
    if (g.wdiv) W = g.W0 + (size_t)(rlocal0 / g.wdiv) * 16384;
    int arow0 = g.amod ? (rlocal0 % g.amod) : (g.ashared ? rlocal0 : row0);
    const float* Arow = g.A + (size_t)arow0 * UU;

    int fA_ks = tid & 1, fA_r = tid >> 1;
    int fB_n  = tid & 63, fB_q = (tid >> 6) & 3;
    int aoff  = q * A_Q + wm * 32 + rg;
    int boff  = q * B_Q + wn * 32 + rg;

    float acc[2][4][4];
#pragma unroll
    for (int i = 0; i < 2; i++)
#pragma unroll
        for (int j = 0; j < 4; j++)
#pragma unroll
            for (int e = 0; e < 4; e++) acc[i][j][e] = 0.f;

    for (int k0 = 0; k0 < UU; k0 += 32) {
        if (k0) __syncthreads();

#pragma unroll
        for (int ksl = 0; ksl < 2; ksl++) {
            const uint4* src = W + (size_t)((k0 >> 4) + ksl) * 1024
                             + fB_q * 256 + col0 + fB_n;
            uint4* dst = Bsm + ksl * B_KS + fB_q * B_Q + fB_n;
            CP_ASYNC16(smem_u32(dst), src);
        }
        CP_COMMIT();

        {
            const float4* s = (const float4*)(Arow + (size_t)fA_r * UU + k0 + fA_ks * 16);
            float4 v0 = s[0], v1 = s[1], v2 = s[2], v3 = s[3];
            float v[16] = {v0.x,v0.y,v0.z,v0.w, v1.x,v1.y,v1.z,v1.w,
                           v2.x,v2.y,v2.z,v2.w, v3.x,v3.y,v3.z,v3.w};
            __nv_bfloat16 h[16], m[16];
#pragma unroll
            for (int t = 0; t < 16; t++) bsplit(v[t], h[t], m[t]);
            uint4* ab = Asm + fA_ks * A_KS + fA_r;
#pragma unroll
            for (int qq = 0; qq < 4; qq++)
                ab[qq * A_Q] = make_uint4(
                    bpack(h[2*qq], h[2*qq+1]), bpack(h[2*qq+8], h[2*qq+9]),
                    bpack(m[2*qq], m[2*qq+1]), bpack(m[2*qq+8], m[2*qq+9]));
        }
        CP_WAIT0();
        __syncthreads();

#pragma unroll
        for (int ks = 0; ks < 2; ks++) {
            uint32_t ahi[2][4], amd[2][4];
            uint2 bhi[4], bmd[4];
            const uint4* ap = Asm + ks * A_KS + aoff;
            const uint4* bp = Bsm + ks * B_KS + boff;
#pragma unroll
            for (int i = 0; i < 2; i++) {
                uint4 c0 = ap[i * 16];
                uint4 c1 = ap[i * 16 + 8];
                ahi[i][0] = c0.x; ahi[i][1] = c1.x; ahi[i][2] = c0.y; ahi[i][3] = c1.y;
                amd[i][0] = c0.z; amd[i][1] = c1.z; amd[i][2] = c0.w; amd[i][3] = c1.w;
            }
#pragma unroll
            for (int j = 0; j < 4; j++) {
                uint4 b = bp[j * 8];
                bhi[j] = make_uint2(b.x, b.y);
                bmd[j] = make_uint2(b.z, b.w);
            }
#pragma unroll
            for (int i = 0; i < 2; i++)
#pragma unroll
                for (int j = 0; j < 4; j++) {
                    uint32_t bh[2] = {bhi[j].x, bhi[j].y};
                    uint32_t bm[2] = {bmd[j].x, bmd[j].y};
                    mma16(acc[i][j], amd[i], bh);
                    mma16(acc[i][j], ahi[i], bm);
                    mma16(acc[i][j], ahi[i], bh);
                }
        }
    }

    const float* bias = (stream == 0) ? g.b0 : (stream == 1 ? g.b1 : g.b2);
    const float* rbs  = (stream == 0) ? g.rb0 : (stream == 1 ? g.rb1 : g.rb2);
    int act = (stream == 0) ? g.act0 : (stream == 1 ? g.act1 : g.act2);
    int mm  = (stream == 0) ? g.mm0  : (stream == 1 ? g.mm1  : g.mm2);

#pragma unroll
    for (int i = 0; i < 2; i++) {
#pragma unroll
        for (int p = 0; p < 2; p++) {
            int roff  = wm * 32 + i * 16 + rg + p * 8;
            int rglob = row0 + roff;
            int rloc  = rlocal0 + roff;
            float mk = mm ? g.mask[rloc] : 1.f;
            float dg = g.deg ? g.deg[rloc] : 0.f;
#pragma unroll
            for (int j = 0; j < 4; j++) {
#pragma unroll
                for (int e = 0; e < 2; e++) {
                    int cc = col0 + wn * 32 + j * 8 + q * 2 + e;
                    float v = acc[i][j][p * 2 + e];
                    if (bias)     v += bias[cc];
                    if (g.deg)    v += dg * rbs[cc];
                    if (g.addsrc) v += g.addsrc[(size_t)rglob * UU + cc];
                    if (g.gamma)
                        v = g.gamma[cc] * (v - g.mean[cc]) * rsqrtf(g.var[cc] + 1e-3f)
                            + g.beta[cc];
                    if (mm == 1) v *= mk;
                    if (act)     v *= 1.f / (1.f + __expf(-v));
                    if (mm == 2) v *= mk;
                    g.C[(size_t)rglob * UU + cc] = v;
                }
            }
        }
    }
}

// ---------------- kv[b][d][e] = sum_n pk[b,n,d] * pv[b,n,e] (3xTF32) ----------
__global__ void __launch_bounds__(256, 2) kv_t(const float* __restrict__ pk,
                                               const float* __restrict__ pv,
                                               float* __restrict__ kvout) {
    __shared__ float Ps[32][72];
    __shared__ float Vs[32][72];
    int tid  = threadIdx.x;
    int lane = tid & 31;
    int wid  = tid >> 5;
    int wm   = wid & 1;
    int wn   = wid >> 1;
    int d0 = blockIdx.x * 64, e0 = blockIdx.y * 64, b = blockIdx.z;
    const float* pkb = pk + (size_t)b * NN * UU;
    const float* pvb = pv + (size_t)b * NN * UU;

    float acc[2][2][4];
#pragma unroll
    for (int i = 0; i < 2; i++)
#pragma unroll
        for (int j = 0; j < 2; j++)
#pragma unroll
            for (int e = 0; e < 4; e++) acc[i][j][e] = 0.f;

    int q = lane & 3, rg = lane >> 2;

    for (int n0 = 0; n0 < NN; n0 += 32) {
#pragma unroll
        for (int i = 0; i < 2; i++) {
            int idx = tid + i * 256;
            int kr = idx >> 4, dc = (idx & 15) * 4;
            *(float4*)&Ps[kr][dc] = *(const float4*)(pkb + (size_t)(n0 + kr) * UU + d0 + dc);
            *(float4*)&Vs[kr][dc] = *(const float4*)(pvb + (size_t)(n0 + kr) * UU + e0 + dc);
        }
        __syncthreads();
#pragma unroll
        for (int ks = 0; ks < 4; ks++) {
            int kk = ks * 8;
            uint32_t ahi[2][4], alo[2][4], bhi[2][2], blo[2][2];
#pragma unroll
            for (int i = 0; i < 2; i++) {
                int rr = wm * 32 + i * 16 + rg;
                tsplit(Ps[kk + q    ][rr    ], ahi[i][0], alo[i][0]);
                tsplit(Ps[kk + q    ][rr + 8], ahi[i][1], alo[i][1]);
                tsplit(Ps[kk + q + 4][rr    ], ahi[i][2], alo[i][2]);
                tsplit(Ps[kk + q + 4][rr + 8], ahi[i][3], alo[i][3]);
            }
#pragma unroll
            for (int j = 0; j < 2; j++) {
                int nn = wn * 16 + j * 8 + rg;
                tsplit(Vs[kk + q    ][nn], bhi[j][0], blo[j][0]);
                tsplit(Vs[kk + q + 4][nn], bhi[j][1], blo[j][1]);
            }
#pragma unroll
            for (int i = 0; i < 2; i++)
#pragma unroll
                for (int j = 0; j < 2; j++) {
                    mma8(acc[i][j], alo[i], bhi[j]);
                    mma8(acc[i][j], ahi[i], blo[j]);
                    mma8(acc[i][j], ahi[i], bhi[j]);
                }
        }
        __syncthreads();
    }

    float* out = kvout + (size_t)b * UU * UU;
#pragma unroll
    for (int i = 0; i < 2; i++)
#pragma unroll
        for (int p = 0; p < 2; p++) {
            int dd = d0 + wm * 32 + i * 16 + rg + p * 8;
#pragma unroll
            for (int j = 0; j < 2; j++)
#pragma unroll
                for (int e = 0; e < 2; e++) {
                    int ee = e0 + wn * 16 + j * 8 + q * 2 + e;
                    out[(size_t)dd * UU + ee] = acc[i][j][p * 2 + e];
                }
        }
}

// ---------------- pack_kv ------------------------------------------------------
__global__ void pack_kv(const float* __restrict__ kv, uint4* __restrict__ dst) {
    int b = blockIdx.y;
    int c = blockIdx.x * 256 + threadIdx.x;
    int n = c & 255, q = (c >> 8) & 3, ksg = c >> 10;
    dst[(size_t)b * 16384 + c] = make_cell(kv + (size_t)b * UU * UU, UU, ksg, q, n);
}

// ---------------- host orchestration -----------------------------------------
extern "C" void kernel_launch(void* const* d_in, const int* in_sizes, int n_in,
                              void* d_out, int out_size) {
    const float* x      = (const float*)d_in[0];
    const float* adj    = (const float*)d_in[1];
    const float* mask   = (const float*)d_in[2];
    const float* W_lin  = (const float*)d_in[3];
    const float* b_lin  = (const float*)d_in[4];
    const float* Wq_mp  = (const float*)d_in[5];
    const float* bq_mp  = (const float*)d_in[6];
    const float* Wk_mp  = (const float*)d_in[7];
    const float* bk_mp  = (const float*)d_in[8];
    const float* Wv_mp  = (const float*)d_in[9];
    const float* bv_mp  = (const float*)d_in[10];
    const float* Wk_att = (const float*)d_in[11];
    const float* Wv_att = (const float*)d_in[12];
    const float* Wq_att = (const float*)d_in[13];
    const float* Wo_att = (const float*)d_in[14];
    const float* gamma  = (const float*)d_in[15];
    const float* beta   = (const float*)d_in[16];
    const float* mean   = (const float*)d_in[17];
    const float* var    = (const float*)d_in[18];
    const float* W_proj = (const float*)d_in[19];
    const float* b_proj = (const float*)d_in[20];
    const float* W_res  = (const float*)d_in[21];
    const float* b_res  = (const float*)d_in[22];

    float *h, *y, *qkv, *t3, *kv, *bvec, *deg;
    uint4 *kvp, *wp;
    cudaGetSymbolAddress((void**)&h,    g_h);
    cudaGetSymbolAddress((void**)&y,    g_y);
    cudaGetSymbolAddress((void**)&qkv,  g_qkv);
    cudaGetSymbolAddress((void**)&t3,   g_t3);
    cudaGetSymbolAddress((void**)&kv,   g_kv);
    cudaGetSymbolAddress((void**)&kvp,  g_kvp);
    cudaGetSymbolAddress((void**)&wp,   g_wp);
    cudaGetSymbolAddress((void**)&bvec, g_bvec);
    cudaGetSymbolAddress((void**)&deg,  g_deg);

    const uint4* P_qmp  = wp + 1  * 16384;
    const uint4* P_kmp  = wp + 4  * 16384;
    const uint4* P_vmp  = wp + 7  * 16384;
    const uint4* P_katt = wp + 10 * 16384;
    const uint4* P_vatt = wp + 11 * 16384;
    const uint4* P_oatt = wp + 13 * 16384;
    const uint4* P_proj = wp + 14 * 16384;
    const uint4* P_res  = wp + 15 * 16384;
    const uint4* P_fq0  = wp + 16 * 16384;   // W_lin @ Wq_mp0
    const uint4* P_fk0  = wp + 17 * 16384;
    const uint4* P_fv0  = wp + 18 * 16384;

    {
        WTptrs p;
        p.src[0] = W_lin;
        p.src[1] = Wq_mp;  p.src[2] = Wq_mp + UU*UU;  p.src[3] = Wq_mp + 2*UU*UU;
        p.src[4] = Wk_mp;  p.src[5] = Wk_mp + UU*UU;  p.src[6] = Wk_mp + 2*UU*UU;
        p.src[7] = Wv_mp;  p.src[8] = Wv_mp + UU*UU;  p.src[9] = Wv_mp + 2*UU*UU;
        p.src[10] = Wk_att; p.src[11] = Wv_att; p.src[12] = Wq_att; p.src[13] = Wo_att;
        p.src[14] = W_proj; p.src[15] = W_res;
        packall<<<dim3(64, 22), 256>>>(p, wp, bvec, b_lin);   // launch 1
    }

    cudaFuncSetAttribute(gemm6, cudaFuncAttributeMaxDynamicSharedMemorySize, SMEM_G);

    dim3 g1(MROWS / 128, UU / 64);         // 512 CTAs
    dim3 g2(2 * MROWS / 128, UU / 64);     // 1024 CTAs
    dim3 g3(3 * MROWS / 128, UU / 64);     // 1536 CTAs
    dim3 gS(2048 / 128, UU / 64);          // 64 CTAs

    csr_build<<<MROWS / 8, 256>>>(adj);    // launch 2

    // mp iteration 0 (W_lin folded):  s = adj@x ; qkv = silu(s@W' + deg*bvec + b)
    spmm<<<MROWS / 4, 256>>>(x, t3);       // launch 3
    { GemmArgs a = {}; a.A = t3; a.ashared = 1;
      a.W0 = P_fq0; a.W1 = P_fk0; a.W2 = P_fv0;
      a.b0 = bq_mp; a.b1 = bk_mp; a.b2 = bv_mp;
      a.deg = deg; a.rb0 = bvec; a.rb1 = bvec + UU; a.rb2 = bvec + 2 * UU;
      a.act0 = a.act1 = a.act2 = 1; a.C = qkv;
      gemm6<<<g3, 256, SMEM_G>>>(a); }     // launch 4  <-- ncu capture slot

    // mp iterations 1..5
    for (int it = 1; it < 6; it++) {
        int i = it >> 1;
        spmm<<<3 * MROWS / 4, 256>>>(qkv, t3);
        GemmArgs a = {}; a.A = t3;
        a.W0 = P_qmp + (size_t)i * 16384;
        a.W1 = P_kmp + (size_t)i * 16384;
        a.W2 = P_vmp + (size_t)i * 16384;
        a.b0 = bq_mp + i * UU; a.b1 = bk_mp + i * UU; a.b2 = bv_mp + i * UU;
        a.act0 = a.act1 = a.act2 = 1;
        if (it == 5) { a.mm0 = a.mm1 = a.mm2 = 2; a.mask = mask; }
        a.C = qkv;
        gemm6<<<g3, 256, SMEM_G>>>(a);
    }

    // attention projections (k, v): pk = silu((k@Wk)*m) ; pv = (v@Wv)*m
    { GemmArgs a = {}; a.A = qkv + (size_t)MROWS * UU;
      a.W0 = P_katt; a.W1 = P_vatt;
      a.act0 = 1; a.mm0 = 1; a.mm1 = 1; a.mask = mask;
      a.C = t3 + (size_t)MROWS * UU;
      gemm6<<<g2, 256, SMEM_G>>>(a); }

    // kv[b] = pk^T @ pv, pack
    kv_t<<<dim3(UU / 64, UU / 64, BB), 256>>>(t3 + (size_t)MROWS * UU,
                                              t3 + (size_t)2 * MROWS * UU, kv);
    pack_kv<<<dim3(64, BB), 256>>>(kv, kvp);

    // T1[b] = Wq_att @ kv[b]
    { GemmArgs a = {}; a.A = Wq_att; a.amod = UU; a.W0 = kvp; a.wdiv = UU; a.C = h;
      gemm6<<<gS, 256, SMEM_G>>>(a); }

    // M[b] = T1[b] @ Wo
    { GemmArgs a = {}; a.A = h; a.W0 = P_oatt; a.C = kv;
      gemm6<<<gS, 256, SMEM_G>>>(a); }
    pack_kv<<<dim3(64, BB), 256>>>(kv, kvp);

    // y = BN(q @ M[b] + x)
    { GemmArgs a = {}; a.A = qkv; a.W0 = kvp; a.wdiv = NN; a.addsrc = x;
      a.gamma = gamma; a.beta = beta; a.mean = mean; a.var = var; a.C = y;
      gemm6<<<g1, 256, SMEM_G>>>(a); }

    // p = silu(y @ W_proj + b_proj)
    { GemmArgs a = {}; a.A = y; a.W0 = P_proj; a.b0 = b_proj; a.act0 = 1; a.C = t3;
      gemm6<<<g1, 256, SMEM_G>>>(a); }

    // out = (p + x @ W_res + b_res) * mask
    { GemmArgs a = {}; a.A = x; a.W0 = P_res; a.b0 = b_res; a.addsrc = t3;
      a.mm0 = 2; a.mask = mask; a.C = (float*)d_out;
      gemm6<<<g1, 256, SMEM_G>>>(a); }
}

// round 16
// speedup vs baseline: 1.5734x; 1.1430x over previous
#include <cuda_runtime.h>
#include <cuda_bf16.h>
#include <cstdint>
#include <math.h>

#define BB 8
#define NN 2048
#define UU 256
#define MROWS (BB*NN)     // 16384
#define TROWS (3*MROWS)   // 49152
#define MAXNBR 128

// ---------------- device scratch ---------------------------------------------
__device__ float g_h  [MROWS*UU];
__device__ float g_y  [MROWS*UU];
__device__ float g_qkv[3*MROWS*UU];
__device__ float g_t3 [3*MROWS*UU];
__device__ float g_kv [BB*UU*UU];
__device__ uint4 g_apack[64*TROWS];      // packed A cells: [plane 64][row TROWS]
__device__ uint4 g_kvp[BB*16384];
__device__ uint4 g_wp [19*16384];
__device__ float g_bvec[3*UU];
__device__ float g_deg[MROWS];
__device__ int   g_cols[MROWS*MAXNBR];
__device__ int   g_cnt [MROWS];

// ---------------- helpers -----------------------------------------------------
__device__ __forceinline__ void tsplit(float x, uint32_t& hi, uint32_t& lo) {
    asm("cvt.rna.tf32.f32 %0, %1;" : "=r"(hi) : "f"(x));
    float r = x - __uint_as_float(hi);
    asm("cvt.rna.tf32.f32 %0, %1;" : "=r"(lo) : "f"(r));
}
__device__ __forceinline__ void mma8(float c[4], const uint32_t a[4], const uint32_t b[2]) {
    asm volatile(
        "mma.sync.aligned.m16n8k8.row.col.f32.tf32.tf32.f32 "
        "{%0,%1,%2,%3},{%4,%5,%6,%7},{%8,%9},{%0,%1,%2,%3};"
        : "+f"(c[0]), "+f"(c[1]), "+f"(c[2]), "+f"(c[3])
        : "r"(a[0]), "r"(a[1]), "r"(a[2]), "r"(a[3]), "r"(b[0]), "r"(b[1]));
}
__device__ __forceinline__ void mma16(float c[4], const uint32_t a[4], const uint32_t b[2]) {
    asm volatile(
        "mma.sync.aligned.m16n8k16.row.col.f32.bf16.bf16.f32 "
        "{%0,%1,%2,%3},{%4,%5,%6,%7},{%8,%9},{%0,%1,%2,%3};"
        : "+f"(c[0]), "+f"(c[1]), "+f"(c[2]), "+f"(c[3])
        : "r"(a[0]), "r"(a[1]), "r"(a[2]), "r"(a[3]), "r"(b[0]), "r"(b[1]));
}
__device__ __forceinline__ void bsplit(float x, __nv_bfloat16& h, __nv_bfloat16& m) {
    h = __float2bfloat16(x);
    m = __float2bfloat16(x - __bfloat162float(h));
}
__device__ __forceinline__ uint32_t bpack(__nv_bfloat16 lo, __nv_bfloat16 hi) {
    __nv_bfloat162 t(lo, hi);
    return *reinterpret_cast<uint32_t*>(&t);
}
__device__ __forceinline__ uint32_t smem_u32(const void* p) {
    uint32_t a;
    asm("{ .reg .u64 t; cvta.to.shared.u64 t, %1; cvt.u32.u64 %0, t; }" : "=r"(a) : "l"(p));
    return a;
}
#define CP_ASYNC16(dst, src) \
    asm volatile("cp.async.cg.shared.global [%0], [%1], 16;" :: "r"(dst), "l"(src))
#define CP_COMMIT()  asm volatile("cp.async.commit_group;" ::: "memory")
#define CP_WAIT0()   asm volatile("cp.async.wait_group 0;" ::: "memory")

// ---------------- bf16 cell helpers -------------------------------------------
__device__ __forceinline__ uint4 vals_to_cell(float x0, float x1, float x2, float x3) {
    __nv_bfloat16 h0,m0,h1,m1,h2,m2,h3,m3;
    bsplit(x0,h0,m0); bsplit(x1,h1,m1); bsplit(x2,h2,m2); bsplit(x3,h3,m3);
    return make_uint4(bpack(h0,h1), bpack(h2,h3), bpack(m0,m1), bpack(m2,m3));
}
__device__ __forceinline__ uint4 make_cell(const float* S, int stride,
                                           int ksg, int q, int n) {
    float x0 = S[(size_t)(16 * ksg + 2 * q)     * stride + n];
    float x1 = S[(size_t)(16 * ksg + 2 * q + 1) * stride + n];
    float x2 = S[(size_t)(16 * ksg + 2 * q + 8) * stride + n];
    float x3 = S[(size_t)(16 * ksg + 2 * q + 9) * stride + n];
    return vals_to_cell(x0, x1, x2, x3);
}

// ---------------- packall: weights + fused W_lin@W*_mp0 + bvec ----------------
struct WTptrs { const float* src[16]; };
__global__ void packall(WTptrs p, uint4* __restrict__ dst,
                        float* __restrict__ bvec, const float* __restrict__ b_lin) {
    int y = blockIdx.y;
    if (y < 16) {
        int c = blockIdx.x * 256 + threadIdx.x;
        int n = c & 255, q = (c >> 8) & 3, ksg = c >> 10;
        dst[(size_t)y * 16384 + c] = make_cell(p.src[y], UU, ksg, q, n);
        return;
    }
    if (y < 19) {
        __shared__ float wl[4][UU];
        int s = y - 16;
        const float* Wlin = p.src[0];
        const float* B    = p.src[1 + 3 * s];
        int c = blockIdx.x * 256 + threadIdx.x;
        int n = c & 255, q = (c >> 8) & 3, ksg = c >> 10;
        int k0 = 16 * ksg + 2 * q;
        int kk[4] = {k0, k0 + 1, k0 + 8, k0 + 9};
#pragma unroll
        for (int r = 0; r < 4; r++)
            wl[r][threadIdx.x] = Wlin[(size_t)kk[r] * UU + threadIdx.x];
        __syncthreads();
        float a0 = 0.f, a1 = 0.f, a2 = 0.f, a3 = 0.f;
        for (int m = 0; m < UU; m++) {
            float bm = B[(size_t)m * UU + n];
            a0 += wl[0][m] * bm; a1 += wl[1][m] * bm;
            a2 += wl[2][m] * bm; a3 += wl[3][m] * bm;
        }
        dst[(size_t)y * 16384 + c] = vals_to_cell(a0, a1, a2, a3);
        return;
    }
    if (blockIdx.x == 0) {
        int s = y - 19;
        const float* Wlin = p.src[0];
        const float* B    = p.src[1 + 3 * s];
        int n = threadIdx.x;
        __shared__ float bw[UU];
        float a = 0.f;
        for (int k = 0; k < UU; k++) a += b_lin[k] * Wlin[(size_t)k * UU + n];
        bw[n] = a;
        __syncthreads();
        float acc = 0.f;
        for (int m = 0; m < UU; m++) acc += bw[m] * B[(size_t)m * UU + n];
        bvec[s * UU + n] = acc;
    }
}

// ---------------- CSR build ---------------------------------------------------
__global__ void csr_build(const float* __restrict__ adj) {
    int r    = blockIdx.x * 8 + (threadIdx.x >> 5);
    int lane = threadIdx.x & 31;
    const float4* row = (const float4*)(adj + (size_t)r * NN);
    int base = 0;
    for (int c0 = 0; c0 < NN / 4; c0 += 32) {
        float4 v = row[c0 + lane];
        unsigned m4 = (v.x != 0.f ? 1u : 0u) | (v.y != 0.f ? 2u : 0u)
                    | (v.z != 0.f ? 4u : 0u) | (v.w != 0.f ? 8u : 0u);
        int cnt4 = __popc(m4);
        int inc = cnt4;
#pragma unroll
        for (int o = 1; o < 32; o <<= 1) {
            int t = __shfl_up_sync(0xffffffffu, inc, o);
            if (lane >= o) inc += t;
        }
        int pos = base + inc - cnt4;
        int colbase = (c0 + lane) * 4;
        if (m4 & 1) { if (pos < MAXNBR) g_cols[r * MAXNBR + pos] = colbase;     pos++; }
        if (m4 & 2) { if (pos < MAXNBR) g_cols[r * MAXNBR + pos] = colbase + 1; pos++; }
        if (m4 & 4) { if (pos < MAXNBR) g_cols[r * MAXNBR + pos] = colbase + 2; pos++; }
        if (m4 & 8) { if (pos < MAXNBR) g_cols[r * MAXNBR + pos] = colbase + 3; pos++; }
        base += __shfl_sync(0xffffffffu, inc, 31);
    }
    if (lane == 0) {
        g_cnt[r] = base < MAXNBR ? base : MAXNBR;
        g_deg[r] = (float)base;
    }
}

// ---------------- spmm_p: adj @ x -> packed bf16 cells ------------------------
// Thread t of row r sums k=4t..4t+3; cells assembled via shfl_xor(2);
// smem transpose yields 64B-contiguous (4-row) stores per plane.
__global__ void __launch_bounds__(256) spmm_p(const float* __restrict__ x,
                                              uint4* __restrict__ apack) {
    __shared__ int cols[4][MAXNBR];
    __shared__ uint4 cbuf[4][64];
    int sub = threadIdx.x >> 6;
    int t   = threadIdx.x & 63;
    int r      = blockIdx.x * 4 + sub;
    int rr     = r & (MROWS - 1);
    int stream = r >> 14;
    int cnt = g_cnt[rr];
    for (int i = t; i < cnt; i += 64) cols[sub][i] = g_cols[rr * MAXNBR + i];
    __syncthreads();
    const float* xb = x + ((size_t)stream * MROWS + (size_t)(rr & ~(NN - 1))) * UU;
    float4 s0 = {0,0,0,0}, s1 = {0,0,0,0};
    int j = 0;
    for (; j + 2 <= cnt; j += 2) {
        float4 v0 = *((const float4*)(xb + (size_t)cols[sub][j]     * UU) + t);
        float4 v1 = *((const float4*)(xb + (size_t)cols[sub][j + 1] * UU) + t);
        s0.x += v0.x; s0.y += v0.y; s0.z += v0.z; s0.w += v0.w;
        s1.x += v1.x; s1.y += v1.y; s1.z += v1.z; s1.w += v1.w;
    }
    if (j < cnt) {
        float4 v0 = *((const float4*)(xb + (size_t)cols[sub][j] * UU) + t);
        s0.x += v0.x; s0.y += v0.y; s0.z += v0.z; s0.w += v0.w;
    }
    float4 o = {s0.x + s1.x, s0.y + s1.y, s0.z + s1.z, s0.w + s1.w};

    __nv_bfloat16 h0,m0,h1,m1,h2,m2,h3,m3;
    bsplit(o.x,h0,m0); bsplit(o.y,h1,m1); bsplit(o.z,h2,m2); bsplit(o.w,h3,m3);
    uint32_t hi01 = bpack(h0,h1), hi23 = bpack(h2,h3);
    uint32_t md01 = bpack(m0,m1), md23 = bpack(m2,m3);
    int r4 = t & 3;
    uint32_t sel_hi = (r4 & 2) ? hi01 : hi23;
    uint32_t sel_md = (r4 & 2) ? md01 : md23;
    uint32_t rcv_hi = __shfl_xor_sync(0xffffffffu, sel_hi, 2);
    uint32_t rcv_md = __shfl_xor_sync(0xffffffffu, sel_md, 2);
    uint4 cell = (r4 & 2) ? make_uint4(rcv_hi, hi23, rcv_md, md23)
                          : make_uint4(hi01, rcv_hi, md01, rcv_md);
    int ksg   = t >> 2;
    int qcell = ((r4 & 1) << 1) | (r4 >> 1);
    cbuf[sub][ksg * 4 + qcell] = cell;
    __syncthreads();
    int w = threadIdx.x;
    int row_off = w & 3, plane = w >> 2;
    apack[(size_t)plane * TROWS + blockIdx.x * 4 + row_off] = cbuf[row_off][plane];
}

// ---------------- 3xBF16 GEMM (templated on packed-A) -------------------------
struct GemmArgs {
    const float* A;
    const uint4* Apack;
    const uint4* W0; const uint4* W1; const uint4* W2;
    const float* b0; const float* b1; const float* b2;
    float* C;
    const float* addsrc;
    const float* mask;
    const float* gamma; const float* beta; const float* mean; const float* var;
    const float* deg;
    const float* rb0; const float* rb1; const float* rb2;
    int act0, act1, act2;
    int mm0, mm1, mm2;
    int ashared;
    int amod;
    int wdiv;
};

#define A_Q  130
#define A_KS 524
#define B_Q  66
#define B_KS 264
#define SMEM_G ((2*A_KS + 2*B_KS) * (int)sizeof(uint4))   // 25,216 B

template <int PACKED>
__global__ void __launch_bounds__(256, PACKED ? 3 : 2) gemm6(GemmArgs g) {
    extern __shared__ __align__(16) uint4 sm4[];
    uint4* Asm = sm4;
    uint4* Bsm = sm4 + 2 * A_KS;

    int tid  = threadIdx.x;
    int lane = tid & 31;
    int wid  = tid >> 5;
    int wm   = wid & 3;
    int wn   = wid >> 2;
    int q    = lane & 3;
    int rg   = lane >> 2;
    int row0 = blockIdx.x * 128;
    int col0 = blockIdx.y * 64;
    int stream  = blockIdx.x >> 7;
    int rlocal0 = row0 - stream * MROWS;

    const uint4* W = (stream == 0) ? g.W0 : (stream == 1 ? g.W1 : g.W2);
    if (g.wdiv) W = g.W0 + (size_t)(rlocal0 / g.wdiv) * 16384;
    int arow0 = g.amod ? (rlocal0 % g.amod) : (g.ashared ? rlocal0 : row0);
    const float* Arow = g.A + (size_t)arow0 * UU;

    int fA_ks = tid & 1, fA_r = tid >> 1;        // float-A fill
    int pA_r  = tid & 127, pA_qh = tid >> 7;     // packed-A fill
    int fB_n  = tid & 63, fB_q = (tid >> 6) & 3;
    int aoff  = q * A_Q + wm * 32 + rg;
    int boff  = q * B_Q + wn * 32 + rg;

    float acc[2][4][4];
#pragma unroll
    for (int i = 0; i < 2; i++)
#pragma unroll
        for (int j = 0; j < 4; j++)
#pragma unroll
            for (int e = 0; e < 4; e++) acc[i][j][e] = 0.f;

    for (int k0 = 0; k0 < UU; k0 += 32) {
        if (k0) __syncthreads();

#pragma unroll
        for (int ksl = 0; ksl < 2; ksl++) {
            const uint4* src = W + (size_t)((k0 >> 4) + ksl) * 1024
                             + fB_q * 256 + col0 + fB_n;
            uint4* dst = Bsm + ksl * B_KS + fB_q * B_Q + fB_n;
            CP_ASYNC16(smem_u32(dst), src);
        }

        if (PACKED) {
#pragma unroll
            for (int ksl = 0; ksl < 2; ksl++)
#pragma unroll
                for (int qq = 0; qq < 2; qq++) {
                    int qc = pA_qh * 2 + qq;
                    const uint4* src = g.Apack
                        + (size_t)(((k0 >> 4) + ksl) * 4 + qc) * TROWS
                        + arow0 + pA_r;
                    uint4* dst = Asm + ksl * A_KS + qc * A_Q + pA_r;
                    CP_ASYNC16(smem_u32(dst), src);
                }
            CP_COMMIT();
        } else {
            CP_COMMIT();
            const float4* s = (const float4*)(Arow + (size_t)fA_r * UU + k0 + fA_ks * 16);
            float4 v0 = s[0], v1 = s[1], v2 = s[2], v3 = s[3];
            float v[16] = {v0.x,v0.y,v0.z,v0.w, v1.x,v1.y,v1.z,v1.w,
                           v2.x,v2.y,v2.z,v2.w, v3.x,v3.y,v3.z,v3.w};
            __nv_bfloat16 h[16], m[16];
#pragma unroll
            for (int t = 0; t < 16; t++) bsplit(v[t], h[t], m[t]);
            uint4* ab = Asm + fA_ks * A_KS + fA_r;
#pragma unroll
            for (int qq = 0; qq < 4; qq++)
                ab[qq * A_Q] = make_uint4(
                    bpack(h[2*qq], h[2*qq+1]), bpack(h[2*qq+8], h[2*qq+9]),
                    bpack(m[2*qq], m[2*qq+1]), bpack(m[2*qq+8], m[2*qq+9]));
        }
        CP_WAIT0();
        __syncthreads();

#pragma unroll
        for (int ks = 0; ks < 2; ks++) {
            uint32_t ahi[2][4], amd[2][4];
            uint2 bhi[4], bmd[4];
            const uint4* ap = Asm + ks * A_KS + aoff;
            const uint4* bp = Bsm + ks * B_KS + boff;
#pragma unroll
            for (int i = 0; i < 2; i++) {
                uint4 c0 = ap[i * 16];
                uint4 c1 = ap[i * 16 + 8];
                ahi[i][0] = c0.x; ahi[i][1] = c1.x; ahi[i][2] = c0.y; ahi[i][3] = c1.y;
                amd[i][0] = c0.z; amd[i][1] = c1.z; amd[i][2] = c0.w; amd[i][3] = c1.w;
            }
#pragma unroll
            for (int j = 0; j < 4; j++) {
                uint4 b = bp[j * 8];
                bhi[j] = make_uint2(b.x, b.y);
                bmd[j] = make_uint2(b.z, b.w);
            }
#pragma unroll
            for (int i = 0; i < 2; i++)
#pragma unroll
                for (int j = 0; j < 4; j++) {
                    uint32_t bh[2] = {bhi[j].x, bhi[j].y};
                    uint32_t bm[2] = {bmd[j].x, bmd[j].y};
                    mma16(acc[i][j], amd[i], bh);
                    mma16(acc[i][j], ahi[i], bm);
                    mma16(acc[i][j], ahi[i], bh);
                }
        }
    }

    const float* bias = (stream == 0) ? g.b0 : (stream == 1 ? g.b1 : g.b2);
    const float* rbs  = (stream == 0) ? g.rb0 : (stream == 1 ? g.rb1 : g.rb2);
    int act = (stream == 0) ? g.act0 : (stream == 1 ? g.act1 : g.act2);
    int mm  = (stream == 0) ? g.mm0  : (stream == 1 ? g.mm1  : g.mm2);

#pragma unroll
    for (int i = 0; i < 2; i++) {
#pragma unroll
        for (int p = 0; p < 2; p++) {
            int roff  = wm * 32 + i * 16 + rg + p * 8;
            int rglob = row0 + roff;
            int rloc  = rlocal0 + roff;
            float mk = mm ? g.mask[rloc] : 1.f;
            float dg = g.deg ? g.deg[rloc] : 0.f;
#pragma unroll
            for (int j = 0; j < 4; j++) {
#pragma unroll
                for (int e = 0; e < 2; e++) {
                    int cc = col0 + wn * 32 + j * 8 + q * 2 + e;
                    float v = acc[i][j][p * 2 + e];
                    if (bias)     v += bias[cc];
                    if (g.deg)    v += dg * rbs[cc];
                    if (g.addsrc) v += g.addsrc[(size_t)rglob * UU + cc];
                    if (g.gamma)
                        v = g.gamma[cc] * (v - g.mean[cc]) * rsqrtf(g.var[cc] + 1e-3f)
                            + g.beta[cc];
                    if (mm == 1) v *= mk;
                    if (act)     v *= 1.f / (1.f + __expf(-v));
                    if (mm == 2) v *= mk;
                    g.C[(size_t)rglob * UU + cc] = v;
                }
            }
        }
    }
}

// ---------------- kv[b][d][e] = sum_n pk[b,n,d] * pv[b,n,e] (3xTF32) ----------
__global__ void __launch_bounds__(256, 2) kv_t(const float* __restrict__ pk,
                                               const float* __restrict__ pv,
                                               float* __restrict__ kvout) {
    __shared__ float Ps[32][72];
    __shared__ float Vs[32][72];
    int tid  = threadIdx.x;
    int lane = tid & 31;
    int wid  = tid >> 5;
    int wm   = wid & 1;
    int wn   = wid >> 1;
    int d0 = blockIdx.x * 64, e0 = blockIdx.y * 64, b = blockIdx.z;
    const float* pkb = pk + (size_t)b * NN * UU;
    const float* pvb = pv + (size_t)b * NN * UU;

    float acc[2][2][4];
#pragma unroll
    for (int i = 0; i < 2; i++)
#pragma unroll
        for (int j = 0; j < 2; j++)
#pragma unroll
            for (int e = 0; e < 4; e++) acc[i][j][e] = 0.f;

    int q = lane & 3, rg = lane >> 2;

    for (int n0 = 0; n0 < NN; n0 += 32) {
#pragma unroll
        for (int i = 0; i < 2; i++) {
            int idx = tid + i * 256;
            int kr = idx >> 4, dc = (idx & 15) * 4;
            *(float4*)&Ps[kr][dc] = *(const float4*)(pkb + (size_t)(n0 + kr) * UU + d0 + dc);
            *(float4*)&Vs[kr][dc] = *(const float4*)(pvb + (size_t)(n0 + kr) * UU + e0 + dc);
        }
        __syncthreads();
#pragma unroll
        for (int ks = 0; ks < 4; ks++) {
            int kk = ks * 8;
            uint32_t ahi[2][4], alo[2][4], bhi[2][2], blo[2][2];
#pragma unroll
            for (int i = 0; i < 2; i++) {
                int rr = wm * 32 + i * 16 + rg;
                tsplit(Ps[kk + q    ][rr    ], ahi[i][0], alo[i][0]);
                tsplit(Ps[kk + q    ][rr + 8], ahi[i][1], alo[i][1]);
                tsplit(Ps[kk + q + 4][rr    ], ahi[i][2], alo[i][2]);
                tsplit(Ps[kk + q + 4][rr + 8], ahi[i][3], alo[i][3]);
            }
#pragma unroll
            for (int j = 0; j < 2; j++) {
                int nn = wn * 16 + j * 8 + rg;
                tsplit(Vs[kk + q    ][nn], bhi[j][0], blo[j][0]);
                tsplit(Vs[kk + q + 4][nn], bhi[j][1], blo[j][1]);
            }
#pragma unroll
            for (int i = 0; i < 2; i++)
#pragma unroll
                for (int j = 0; j < 2; j++) {
                    mma8(acc[i][j], alo[i], bhi[j]);
                    mma8(acc[i][j], ahi[i], blo[j]);
                    mma8(acc[i][j], ahi[i], bhi[j]);
                }
        }
        __syncthreads();
    }

    float* out = kvout + (size_t)b * UU * UU;
#pragma unroll
    for (int i = 0; i < 2; i++)
#pragma unroll
        for (int p = 0; p < 2; p++) {
            int dd = d0 + wm * 32 + i * 16 + rg + p * 8;
#pragma unroll
            for (int j = 0; j < 2; j++)
#pragma unroll
                for (int e = 0; e < 2; e++) {
                    int ee = e0 + wn * 16 + j * 8 + q * 2 + e;
                    out[(size_t)dd * UU + ee] = acc[i][j][p * 2 + e];
                }
        }
}

// ---------------- pack_kv ------------------------------------------------------
__global__ void pack_kv(const float* __restrict__ kv, uint4* __restrict__ dst) {
    int b = blockIdx.y;
    int c = blockIdx.x * 256 + threadIdx.x;
    int n = c & 255, q = (c >> 8) & 3, ksg = c >> 10;
    dst[(size_t)b * 16384 + c] = make_cell(kv + (size_t)b * UU * UU, UU, ksg, q, n);
}

// ---------------- host orchestration -----------------------------------------
extern "C" void kernel_launch(void* const* d_in, const int* in_sizes, int n_in,
                              void* d_out, int out_size) {
    const float* x      = (const float*)d_in[0];
    const float* adj    = (const float*)d_in[1];
    const float* mask   = (const float*)d_in[2];
    const float* W_lin  = (const float*)d_in[3];
    const float* b_lin  = (const float*)d_in[4];
    const float* Wq_mp  = (const float*)d_in[5];
    const float* bq_mp  = (const float*)d_in[6];
    const float* Wk_mp  = (const float*)d_in[7];
    const float* bk_mp  = (const float*)d_in[8];
    const float* Wv_mp  = (const float*)d_in[9];
    const float* bv_mp  = (const float*)d_in[10];
    const float* Wk_att = (const float*)d_in[11];
    const float* Wv_att = (const float*)d_in[12];
    const float* Wq_att = (const float*)d_in[13];
    const float* Wo_att = (const float*)d_in[14];
    const float* gamma  = (const float*)d_in[15];
    const float* beta   = (const float*)d_in[16];
    const float* mean   = (const float*)d_in[17];
    const float* var    = (const float*)d_in[18];
    const float* W_proj = (const float*)d_in[19];
    const float* b_proj = (const float*)d_in[20];
    const float* W_res  = (const float*)d_in[21];
    const float* b_res  = (const float*)d_in[22];

    float *h, *y, *qkv, *t3, *kv, *bvec, *deg;
    uint4 *kvp, *wp, *apack;
    cudaGetSymbolAddress((void**)&h,     g_h);
    cudaGetSymbolAddress((void**)&y,     g_y);
    cudaGetSymbolAddress((void**)&qkv,   g_qkv);
    cudaGetSymbolAddress((void**)&t3,    g_t3);
    cudaGetSymbolAddress((void**)&kv,    g_kv);
    cudaGetSymbolAddress((void**)&kvp,   g_kvp);
    cudaGetSymbolAddress((void**)&wp,    g_wp);
    cudaGetSymbolAddress((void**)&apack, g_apack);
    cudaGetSymbolAddress((void**)&bvec,  g_bvec);
    cudaGetSymbolAddress((void**)&deg,   g_deg);

    const uint4* P_qmp  = wp + 1  * 16384;
    const uint4* P_kmp  = wp + 4  * 16384;
    const uint4* P_vmp  = wp + 7  * 16384;
    const uint4* P_katt = wp + 10 * 16384;
    const uint4* P_vatt = wp + 11 * 16384;
    const uint4* P_oatt = wp + 13 * 16384;
    const uint4* P_proj = wp + 14 * 16384;
    const uint4* P_res  = wp + 15 * 16384;
    const uint4* P_fq0  = wp + 16 * 16384;
    const uint4* P_fk0  = wp + 17 * 16384;
    const uint4* P_fv0  = wp + 18 * 16384;

    {
        WTptrs p;
        p.src[0] = W_lin;
        p.src[1] = Wq_mp;  p.src[2] = Wq_mp + UU*UU;  p.src[3] = Wq_mp + 2*UU*UU;
        p.src[4] = Wk_mp;  p.src[5] = Wk_mp + UU*UU;  p.src[6] = Wk_mp + 2*UU*UU;
        p.src[7] = Wv_mp;  p.src[8] = Wv_mp + UU*UU;  p.src[9] = Wv_mp + 2*UU*UU;
        p.src[10] = Wk_att; p.src[11] = Wv_att; p.src[12] = Wq_att; p.src[13] = Wo_att;
        p.src[14] = W_proj; p.src[15] = W_res;
        packall<<<dim3(64, 22), 256>>>(p, wp, bvec, b_lin);   // launch 1
    }

    cudaFuncSetAttribute(gemm6<0>, cudaFuncAttributeMaxDynamicSharedMemorySize, SMEM_G);
    cudaFuncSetAttribute(gemm6<1>, cudaFuncAttributeMaxDynamicSharedMemorySize, SMEM_G);

    dim3 g1(MROWS / 128, UU / 64);
    dim3 g2(2 * MROWS / 128, UU / 64);
    dim3 g3(3 * MROWS / 128, UU / 64);
    dim3 gS(2048 / 128, UU / 64);

    csr_build<<<MROWS / 8, 256>>>(adj);    // launch 2

    // mp iteration 0 (W_lin folded): s = adj@x packed; qkv = silu(s@W' + deg*bvec + b)
    spmm_p<<<MROWS / 4, 256>>>(x, apack);  // launch 3
    { GemmArgs a = {}; a.Apack = apack; a.ashared = 1;
      a.W0 = P_fq0; a.W1 = P_fk0; a.W2 = P_fv0;
      a.b0 = bq_mp; a.b1 = bk_mp; a.b2 = bv_mp;
      a.deg = deg; a.rb0 = bvec; a.rb1 = bvec + UU; a.rb2 = bvec + 2 * UU;
      a.act0 = a.act1 = a.act2 = 1; a.C = qkv;
      gemm6<1><<<g3, 256, SMEM_G>>>(a); }  // launch 4 <-- ncu slot (packed gemm)

    // mp iterations 1..5
    for (int it = 1; it < 6; it++) {
        int i = it >> 1;
        spmm_p<<<3 * MROWS / 4, 256>>>(qkv, apack);
        GemmArgs a = {}; a.Apack = apack;
        a.W0 = P_qmp + (size_t)i * 16384;
        a.W1 = P_kmp + (size_t)i * 16384;
        a.W2 = P_vmp + (size_t)i * 16384;
        a.b0 = bq_mp + i * UU; a.b1 = bk_mp + i * UU; a.b2 = bv_mp + i * UU;
        a.act0 = a.act1 = a.act2 = 1;
        if (it == 5) { a.mm0 = a.mm1 = a.mm2 = 2; a.mask = mask; }
        a.C = qkv;
        gemm6<1><<<g3, 256, SMEM_G>>>(a);
    }

    // attention projections (k, v): pk = silu((k@Wk)*m) ; pv = (v@Wv)*m
    { GemmArgs a = {}; a.A = qkv + (size_t)MROWS * UU;
      a.W0 = P_katt; a.W1 = P_vatt;
      a.act0 = 1; a.mm0 = 1; a.mm1 = 1; a.mask = mask;
      a.C = t3 + (size_t)MROWS * UU;
      gemm6<0><<<g2, 256, SMEM_G>>>(a); }

    // kv[b] = pk^T @ pv, pack
    kv_t<<<dim3(UU / 64, UU / 64, BB), 256>>>(t3 + (size_t)MROWS * UU,
                                              t3 + (size_t)2 * MROWS * UU, kv);
    pack_kv<<<dim3(64, BB), 256>>>(kv, kvp);

    // T1[b] = Wq_att @ kv[b]
    { GemmArgs a = {}; a.A = Wq_att; a.amod = UU; a.W0 = kvp; a.wdiv = UU; a.C = h;
      gemm6<0><<<gS, 256, SMEM_G>>>(a); }

    // M[b] = T1[b] @ Wo
    { GemmArgs a = {}; a.A = h; a.W0 = P_oatt; a.C = kv;
      gemm6<0><<<gS, 256, SMEM_G>>>(a); }
    pack_kv<<<dim3(64, BB), 256>>>(kv, kvp);

    // y = BN(q @ M[b] + x)
    { GemmArgs a = {}; a.A = qkv; a.W0 = kvp; a.wdiv = NN; a.addsrc = x;
      a.gamma = gamma; a.beta = beta; a.mean = mean; a.var = var; a.C = y;
      gemm6<0><<<g1, 256, SMEM_G>>>(a); }

    // p = silu(y @ W_proj + b_proj)
    { GemmArgs a = {}; a.A = y; a.W0 = P_proj; a.b0 = b_proj; a.act0 = 1; a.C = t3;
      gemm6<0><<<g1, 256, SMEM_G>>>(a); }

    // out = (p + x @ W_res + b_res) * mask
    { GemmArgs a = {}; a.A = x; a.W0 = P_res; a.b0 = b_res; a.addsrc = t3;
      a.mm0 = 2; a.mask = mask; a.C = (float*)d_out;
      gemm6<0><<<g1, 256, SMEM_G>>>(a); }
}